// round 6
// baseline (speedup 1.0000x reference)
#include <cuda_runtime.h>
#include <stdint.h>

// ---------------------------------------------------------------------------
// Problem constants (DSEC 480x640, 4x4 voxels, B=4)
// ---------------------------------------------------------------------------
#define NV0 120
#define NV1 160
#define NBATCH 4
#define KC (NBATCH * NV0 * NV1)   /* 76800 */
#define DIM 64

#define N_MAX (1 << 20)
#define E_MAX (1 << 23)
#define NB 65536                  /* sort buckets */
#define SORT_CAP 4096
#define ENC_NEG_INF 0x007FFFFFu

// int32-wrapped sentinel: (int32)(76800*76800) = 5898240000 - 4294967296
#define SENT32 1603272704
#define SENT64 5898240000ull

// Output layout (float32 flatten, reference return order):
#define OFF_POS   (KC * DIM)
#define OFF_BATCH (OFF_POS + KC * 3)
#define OFF_MASK  (OFF_BATCH + KC)
#define OFF_EI    (OFF_MASK + KC)

// ---------------------------------------------------------------------------
// Static device scratch
// ---------------------------------------------------------------------------
__device__ int          g_is64;
__device__ int          g_cluster[N_MAX];
__device__ unsigned int g_counts[KC];
__device__ float        g_possum[KC * 3];
__device__ unsigned int g_xmax[KC * DIM];
__device__ unsigned int g_low[E_MAX];        // low key bits grouped by bucket
__device__ unsigned int g_bcnt[NB];
__device__ unsigned int g_incl[NB];
__device__ unsigned int g_cursor[NB];

__device__ __forceinline__ unsigned int enc_f32(float v) {
    unsigned int u = __float_as_uint(v);
    return (u & 0x80000000u) ? ~u : (u | 0x80000000u);
}
__device__ __forceinline__ float dec_f32(unsigned int u) {
    u = (u & 0x80000000u) ? (u & 0x7FFFFFFFu) : ~u;
    return __uint_as_float(u);
}
__device__ __forceinline__ int ld_id(const void* p, long long i, int is64) {
    return is64 ? (int)((const long long*)p)[i] : ((const int*)p)[i];
}
__device__ __forceinline__ int clampi(int v, int lo, int hi) {
    return v < lo ? lo : (v > hi ? hi : v);
}

// sort key (monotone u64 matching reference ascending order), ALL edges included
__device__ __forceinline__ unsigned long long edge_uk(int sc, int dc, int is64) {
    if (is64) {
        if (sc == dc) return SENT64;
        return (unsigned long long)(unsigned int)sc * 76800ull
             + (unsigned long long)(unsigned int)dc;
    }
    int key32 = (sc == dc) ? SENT32
              : (int)((unsigned int)sc * 76800u + (unsigned int)dc);  // wraps like ref
    return (unsigned long long)(((unsigned int)key32) ^ 0x80000000u); // signed order
}

// decode + validity from uk
__device__ __forceinline__ void decode_key(unsigned long long uk, int is64,
                                           float* sf, float* df, bool* valid) {
    if (is64) {
        *valid = (uk < SENT64);
        *sf = (float)(long long)(uk / 76800ull);
        *df = (float)(long long)(uk % 76800ull);
    } else {
        long long key = (long long)(int)(((unsigned int)uk) ^ 0x80000000u);
        *valid = (key < (long long)SENT32);
        long long q = key / 76800ll, r = key - q * 76800ll;
        if (r < 0) { q -= 1; r += 76800ll; }   // floor-div semantics (jnp //, %)
        *sf = (float)q;
        *df = (float)r;
    }
}

// ---------------------------------------------------------------------------
// Phase -1: dtype sniff. int64 node ids < 2^31 => every odd 32-bit word is 0.
// ---------------------------------------------------------------------------
__global__ void sniff_kernel(const unsigned int* ew) {
    if (threadIdx.x == 0) {
        unsigned int o = 0;
        for (int k = 1; k < 128; k += 2) o |= ew[k];
        g_is64 = (o == 0u) ? 1 : 0;
    }
}

__global__ void init_kernel() {
    int stride = gridDim.x * blockDim.x;
    for (int i = blockIdx.x * blockDim.x + threadIdx.x; i < KC * DIM; i += stride) {
        g_xmax[i] = ENC_NEG_INF;
        if (i < KC)     g_counts[i] = 0u;
        if (i < KC * 3) g_possum[i] = 0.0f;
        if (i < NB) { g_bcnt[i] = 0u; g_cursor[i] = 0u; }
    }
}

__global__ void cluster_kernel(const float* pos, const void* batch, int N) {
    int i = blockIdx.x * blockDim.x + threadIdx.x;
    if (i >= N) return;
    int is64 = g_is64;
    float p0 = pos[3 * i + 0];
    float p1 = pos[3 * i + 1];
    float p2 = pos[3 * i + 2];
    int c0 = clampi((int)floorf(p1 * 0.25f), 0, NV0 - 1);
    int c1 = clampi((int)floorf(p2 * 0.25f), 0, NV1 - 1);
    int b  = clampi(ld_id(batch, i, is64), 0, NBATCH - 1);
    int c  = c0 + c1 * NV0 + b * (NV0 * NV1);
    g_cluster[i] = c;
    atomicAdd(&g_counts[c], 1u);
    atomicAdd(&g_possum[3 * c + 0], p0);
    atomicAdd(&g_possum[3 * c + 1], p1);
    atomicAdd(&g_possum[3 * c + 2], p2);
}

__global__ void xmax_kernel(const float* x, int N) {
    int warp = (blockIdx.x * blockDim.x + threadIdx.x) >> 5;
    int lane = threadIdx.x & 31;
    if (warp >= N) return;
    int c = g_cluster[warp];
    const float* xr = x + (size_t)warp * DIM;
    unsigned int* dst = g_xmax + (size_t)c * DIM;
    atomicMax(&dst[lane],      enc_f32(xr[lane]));
    atomicMax(&dst[lane + 32], enc_f32(xr[lane + 32]));
}

__global__ void hist_kernel(const void* eidx, int N, int E) {
    int e = blockIdx.x * blockDim.x + threadIdx.x;
    if (e >= E) return;
    int is64 = g_is64;
    int u = clampi(ld_id(eidx, e, is64), 0, N - 1);
    int v = clampi(ld_id(eidx, (long long)E + e, is64), 0, N - 1);
    unsigned long long uk = edge_uk(g_cluster[u], g_cluster[v], is64);
    int sh = is64 ? 17 : 16;
    unsigned int b = (unsigned int)(uk >> sh);
    if (b < NB) atomicAdd(&g_bcnt[b], 1u);
}

// single-block inclusive scan of 65536 = 1024*64 bins
__global__ void scan_kernel() {
    __shared__ unsigned int sums[1024];
    const int PER = NB / 1024;  // 64
    int t = threadIdx.x;
    unsigned int s = 0;
    #pragma unroll 8
    for (int i = 0; i < PER; i++) s += g_bcnt[t * PER + i];
    sums[t] = s;
    __syncthreads();
    for (int d = 1; d < 1024; d <<= 1) {
        unsigned int v = (t >= d) ? sums[t - d] : 0u;
        __syncthreads();
        sums[t] += v;
        __syncthreads();
    }
    unsigned int prefix = (t == 0) ? 0u : sums[t - 1];
    for (int i = 0; i < PER; i++) {
        prefix += g_bcnt[t * PER + i];
        g_incl[t * PER + i] = prefix;
    }
}

__global__ void scatter_kernel(const void* eidx, int N, int E) {
    int e = blockIdx.x * blockDim.x + threadIdx.x;
    if (e >= E) return;
    int is64 = g_is64;
    int u = clampi(ld_id(eidx, e, is64), 0, N - 1);
    int v = clampi(ld_id(eidx, (long long)E + e, is64), 0, N - 1);
    unsigned long long uk = edge_uk(g_cluster[u], g_cluster[v], is64);
    int sh = is64 ? 17 : 16;
    unsigned int b   = (unsigned int)(uk >> sh);
    unsigned int low = (unsigned int)(uk & ((1u << sh) - 1u));
    if (b >= NB) return;
    unsigned int start = (b == 0u) ? 0u : g_incl[b - 1];
    unsigned int pos = start + atomicAdd(&g_cursor[b], 1u);
    if (pos < (unsigned int)E) g_low[pos] = low;
}

__global__ void bucket_emit_kernel(float* out, int E, long long out_size) {
    __shared__ unsigned int s[SORT_CAP];
    unsigned int b     = blockIdx.x;
    unsigned int start = (b == 0u) ? 0u : g_incl[b - 1];
    unsigned int n     = g_incl[b] - start;
    if (n == 0) return;
    int is64 = g_is64;
    int sh = is64 ? 17 : 16;
    const long long off_ei = OFF_EI;
    const long long off_em = off_ei + 2ll * E;

    if (n <= SORT_CAP) {
        unsigned int P = 1;
        while (P < n) P <<= 1;
        for (unsigned int i = threadIdx.x; i < P; i += blockDim.x)
            s[i] = (i < n) ? g_low[start + i] : 0xFFFFFFFFu;
        __syncthreads();
        for (unsigned int k = 2; k <= P; k <<= 1)
            for (unsigned int j = k >> 1; j > 0; j >>= 1) {
                for (unsigned int i = threadIdx.x; i < P; i += blockDim.x) {
                    unsigned int ixj = i ^ j;
                    if (ixj > i) {
                        bool up = ((i & k) == 0);
                        unsigned int a = s[i], c = s[ixj];
                        if ((a > c) == up) { s[i] = c; s[ixj] = a; }
                    }
                }
                __syncthreads();
            }
        for (unsigned int i = threadIdx.x; i < n; i += blockDim.x) {
            unsigned int v = s[i];
            bool first = (i == 0) || (v != s[i - 1]);
            unsigned long long uk = (((unsigned long long)b) << sh) | v;
            float sf, df; bool valid;
            decode_key(uk, is64, &sf, &df, &valid);
            bool mask = first && valid;
            long long p = (long long)(start + i);
            if (off_ei + p < out_size)     out[off_ei + p]     = mask ? sf   : -1.0f;
            if (off_ei + E + p < out_size) out[off_ei + E + p] = mask ? df   : -1.0f;
            if (off_em + p < out_size)     out[off_em + p]     = mask ? 1.0f : 0.0f;
        }
    } else {
        // fallback (large bucket, e.g. the self-loop sentinel bin):
        // all-equal fast path first
        __shared__ int all_eq;
        if (threadIdx.x == 0) all_eq = 1;
        __syncthreads();
        unsigned int v0 = g_low[start];
        for (unsigned int i = threadIdx.x; i < n; i += blockDim.x)
            if (g_low[start + i] != v0) all_eq = 0;
        __syncthreads();
        if (!all_eq) {
            unsigned int* a = g_low + start;
            for (unsigned int pass = 0; pass < n; ++pass) {
                unsigned int st = pass & 1u;
                for (unsigned int i = st + 2u * threadIdx.x; i + 1 < n; i += 2u * blockDim.x) {
                    unsigned int x0 = a[i], x1 = a[i + 1];
                    if (x0 > x1) { a[i] = x1; a[i + 1] = x0; }
                }
                __syncthreads();
            }
        }
        for (unsigned int i = threadIdx.x; i < n; i += blockDim.x) {
            unsigned int v = g_low[start + i];
            bool first = (i == 0) || (v != g_low[start + i - 1]);
            unsigned long long uk = (((unsigned long long)b) << sh) | v;
            float sf, df; bool valid;
            decode_key(uk, is64, &sf, &df, &valid);
            bool mask = first && valid;
            long long p = (long long)(start + i);
            if (off_ei + p < out_size)     out[off_ei + p]     = mask ? sf   : -1.0f;
            if (off_ei + E + p < out_size) out[off_ei + E + p] = mask ? df   : -1.0f;
            if (off_em + p < out_size)     out[off_em + p]     = mask ? 1.0f : 0.0f;
        }
    }
}

__global__ void finalize_kernel(float* out, long long out_size) {
    int i = blockIdx.x * blockDim.x + threadIdx.x;
    if (i >= KC * DIM) return;
    {
        int c = i / DIM;
        float v = (g_counts[c] > 0u) ? dec_f32(g_xmax[i]) : 0.0f;
        if (i < out_size) out[i] = v;
    }
    if (i < KC * 3) {
        int c = i / 3;
        unsigned int cnt = g_counts[c];
        if (OFF_POS + i < out_size)
            out[OFF_POS + i] = g_possum[i] / (float)(cnt > 0u ? cnt : 1u);
    }
    if (i < KC) {
        if (OFF_BATCH + i < out_size) out[OFF_BATCH + i] = (float)(i / (NV0 * NV1));
        if (OFF_MASK + i < out_size)  out[OFF_MASK + i]  = (g_counts[i] > 0u) ? 1.0f : 0.0f;
    }
}

// ---------------------------------------------------------------------------
// Launch: identify inputs by element-count relations (permutation-proof)
// ---------------------------------------------------------------------------
extern "C" void kernel_launch(void* const* d_in, const int* in_sizes, int n_in,
                              void* d_out, int out_size) {
    int ib = 0;
    for (int i = 1; i < n_in && i < 4; i++)
        if (in_sizes[i] < in_sizes[ib]) ib = i;
    long long N = in_sizes[ib];
    int ix = -1, ip = -1, ie = -1;
    for (int i = 0; i < n_in && i < 4; i++) {
        if (i == ib) continue;
        long long s = in_sizes[i];
        if (s == 64 * N)     ix = i;
        else if (s == 3 * N) ip = i;
        else                 ie = i;
    }
    if (ix < 0 || ip < 0 || ie < 0) { ix = 0; ip = 1; ib = 2; ie = 3; }

    const float* x    = (const float*)d_in[ix];
    const float* pos  = (const float*)d_in[ip];
    const void*  bat  = d_in[ib];
    const void*  eidx = d_in[ie];
    float*       out  = (float*)d_out;

    int Ni = (int)N;
    int E  = in_sizes[ie] / 2;
    if (Ni > N_MAX) Ni = N_MAX;
    if (E > E_MAX)  E  = E_MAX;

    const int T = 256;
    sniff_kernel<<<1, 32>>>((const unsigned int*)eidx);
    init_kernel<<<(KC * DIM + T - 1) / T, T>>>();
    cluster_kernel<<<(Ni + T - 1) / T, T>>>(pos, bat, Ni);
    xmax_kernel<<<(int)(((size_t)Ni * 32 + T - 1) / T), T>>>(x, Ni);
    hist_kernel<<<(E + T - 1) / T, T>>>(eidx, Ni, E);
    scan_kernel<<<1, 1024>>>();
    scatter_kernel<<<(E + T - 1) / T, T>>>(eidx, Ni, E);
    bucket_emit_kernel<<<NB, 128>>>(out, E, (long long)out_size);
    finalize_kernel<<<(KC * DIM + T - 1) / T, T>>>(out, (long long)out_size);
}

// round 7
// speedup vs baseline: 1.3629x; 1.3629x over previous
#include <cuda_runtime.h>
#include <stdint.h>

// ---------------------------------------------------------------------------
// Problem constants (DSEC 480x640, 4x4 voxels, B=4)
// ---------------------------------------------------------------------------
#define NV0 120
#define NV1 160
#define NBATCH 4
#define KC (NBATCH * NV0 * NV1)   /* 76800 */
#define DIM 64

#define N_MAX (1 << 20)
#define E_MAX (1 << 23)
#define NB (1 << 20)              /* sort buckets */
#define NBLK (NB / 1024)          /* 1024 scan blocks */
#define ENC_NEG_INF 0x007FFFFFu

// int32-wrapped sentinel: (int32)(76800*76800) = 1603272704
#define SENT32 1603272704
#define SENT64 5898240000ull

// Output layout (float32 flatten, reference return order):
#define OFF_POS   (KC * DIM)
#define OFF_BATCH (OFF_POS + KC * 3)
#define OFF_MASK  (OFF_BATCH + KC)
#define OFF_EI    (OFF_MASK + KC)

// ---------------------------------------------------------------------------
// Static device scratch
// ---------------------------------------------------------------------------
__device__ int          g_is64;
__device__ int          g_cluster[N_MAX];
__device__ unsigned int g_counts[KC];
__device__ float        g_possum[KC * 3];
__device__ unsigned int g_xmax[KC * DIM];
__device__ unsigned int g_low[E_MAX];        // low key bits grouped by bucket
__device__ unsigned int g_bcnt[NB];
__device__ unsigned int g_incl[NB];
__device__ unsigned int g_cursor[NB];
__device__ unsigned int g_bsum[NBLK];

__device__ __forceinline__ unsigned int enc_f32(float v) {
    unsigned int u = __float_as_uint(v);
    return (u & 0x80000000u) ? ~u : (u | 0x80000000u);
}
__device__ __forceinline__ float dec_f32(unsigned int u) {
    u = (u & 0x80000000u) ? (u & 0x7FFFFFFFu) : ~u;
    return __uint_as_float(u);
}
__device__ __forceinline__ int ld_id(const void* p, long long i, int is64) {
    return is64 ? (int)((const long long*)p)[i] : ((const int*)p)[i];
}
__device__ __forceinline__ int clampi(int v, int lo, int hi) {
    return v < lo ? lo : (v > hi ? hi : v);
}

// sort key (monotone u64 matching reference ascending order), ALL edges included
__device__ __forceinline__ unsigned long long edge_uk(int sc, int dc, int is64) {
    if (is64) {
        if (sc == dc) return SENT64;
        return (unsigned long long)(unsigned int)sc * 76800ull
             + (unsigned long long)(unsigned int)dc;
    }
    int key32 = (sc == dc) ? SENT32
              : (int)((unsigned int)sc * 76800u + (unsigned int)dc);  // wraps like ref
    return (unsigned long long)(((unsigned int)key32) ^ 0x80000000u); // signed order
}

// decode + validity from uk
__device__ __forceinline__ void decode_key(unsigned long long uk, int is64,
                                           float* sf, float* df, bool* valid) {
    if (is64) {
        *valid = (uk < SENT64);
        *sf = (float)(long long)(uk / 76800ull);
        *df = (float)(long long)(uk % 76800ull);
    } else {
        long long key = (long long)(int)(((unsigned int)uk) ^ 0x80000000u);
        *valid = (key < (long long)SENT32);
        long long q = key / 76800ll, r = key - q * 76800ll;
        if (r < 0) { q -= 1; r += 76800ll; }   // floor-div (jnp //, %)
        *sf = (float)q;
        *df = (float)r;
    }
}

// ---------------------------------------------------------------------------
__global__ void sniff_kernel(const unsigned int* ew) {
    if (threadIdx.x == 0) {
        unsigned int o = 0;
        for (int k = 1; k < 128; k += 2) o |= ew[k];
        g_is64 = (o == 0u) ? 1 : 0;
    }
}

__global__ void init_kernel() {
    int stride = gridDim.x * blockDim.x;
    for (int i = blockIdx.x * blockDim.x + threadIdx.x; i < KC * DIM; i += stride) {
        g_xmax[i] = ENC_NEG_INF;
        if (i < KC)     g_counts[i] = 0u;
        if (i < KC * 3) g_possum[i] = 0.0f;
        if (i < NB) { g_bcnt[i] = 0u; g_cursor[i] = 0u; }
    }
}

__global__ void cluster_kernel(const float* pos, const void* batch, int N) {
    int i = blockIdx.x * blockDim.x + threadIdx.x;
    if (i >= N) return;
    int is64 = g_is64;
    float p0 = pos[3 * i + 0];
    float p1 = pos[3 * i + 1];
    float p2 = pos[3 * i + 2];
    int c0 = clampi((int)floorf(p1 * 0.25f), 0, NV0 - 1);
    int c1 = clampi((int)floorf(p2 * 0.25f), 0, NV1 - 1);
    int b  = clampi(ld_id(batch, i, is64), 0, NBATCH - 1);
    int c  = c0 + c1 * NV0 + b * (NV0 * NV1);
    g_cluster[i] = c;
    atomicAdd(&g_counts[c], 1u);
    atomicAdd(&g_possum[3 * c + 0], p0);
    atomicAdd(&g_possum[3 * c + 1], p1);
    atomicAdd(&g_possum[3 * c + 2], p2);
}

// one warp per node: one float2 load covers the 64-float row; 2 atomics/lane
__global__ void xmax_kernel(const float* __restrict__ x, int N) {
    int warp = (blockIdx.x * blockDim.x + threadIdx.x) >> 5;
    int lane = threadIdx.x & 31;
    if (warp >= N) return;
    int c = g_cluster[warp];
    float2 v = ((const float2*)(x + (size_t)warp * DIM))[lane];
    unsigned int* dst = g_xmax + (size_t)c * DIM;
    atomicMax(&dst[2 * lane],     enc_f32(v.x));
    atomicMax(&dst[2 * lane + 1], enc_f32(v.y));
}

__global__ void hist_kernel(const void* eidx, int N, int E) {
    int e = blockIdx.x * blockDim.x + threadIdx.x;
    if (e >= E) return;
    int is64 = g_is64;
    int u = clampi(ld_id(eidx, e, is64), 0, N - 1);
    int v = clampi(ld_id(eidx, (long long)E + e, is64), 0, N - 1);
    unsigned long long uk = edge_uk(g_cluster[u], g_cluster[v], is64);
    int sh = is64 ? 13 : 12;
    unsigned int b = (unsigned int)(uk >> sh);
    if (b < NB) atomicAdd(&g_bcnt[b], 1u);
}

// -- multi-block inclusive scan of NB bins --------------------------------
__global__ void scan1_kernel() {      // NBLK blocks x 1024
    __shared__ unsigned int s[1024];
    int t = threadIdx.x;
    int base = blockIdx.x * 1024;
    s[t] = g_bcnt[base + t];
    __syncthreads();
    for (int d = 1; d < 1024; d <<= 1) {
        unsigned int u = (t >= d) ? s[t - d] : 0u;
        __syncthreads();
        s[t] += u;
        __syncthreads();
    }
    g_incl[base + t] = s[t];
    if (t == 1023) g_bsum[blockIdx.x] = s[t];
}
__global__ void scan2_kernel() {      // 1 block x 1024: bsum -> exclusive
    __shared__ unsigned int s[1024];
    int t = threadIdx.x;
    unsigned int orig = g_bsum[t];
    s[t] = orig;
    __syncthreads();
    for (int d = 1; d < 1024; d <<= 1) {
        unsigned int u = (t >= d) ? s[t - d] : 0u;
        __syncthreads();
        s[t] += u;
        __syncthreads();
    }
    g_bsum[t] = s[t] - orig;          // exclusive
}
__global__ void scan3_kernel() {      // add block offsets
    int i = blockIdx.x * blockDim.x + threadIdx.x;
    if (i < NB) g_incl[i] += g_bsum[i >> 10];
}

__global__ void scatter_kernel(const void* eidx, int N, int E) {
    int e = blockIdx.x * blockDim.x + threadIdx.x;
    if (e >= E) return;
    int is64 = g_is64;
    int u = clampi(ld_id(eidx, e, is64), 0, N - 1);
    int v = clampi(ld_id(eidx, (long long)E + e, is64), 0, N - 1);
    unsigned long long uk = edge_uk(g_cluster[u], g_cluster[v], is64);
    int sh = is64 ? 13 : 12;
    unsigned int b   = (unsigned int)(uk >> sh);
    unsigned int low = (unsigned int)(uk & ((1u << sh) - 1u));
    if (b >= NB) return;
    unsigned int start = (b == 0u) ? 0u : g_incl[b - 1];
    unsigned int pos = start + atomicAdd(&g_cursor[b], 1u);
    if (pos < (unsigned int)E) g_low[pos] = low;
}

// one WARP per bucket: register bitonic sort via shfl (no block barriers)
__global__ void bucket_emit_kernel(float* __restrict__ out, int E, long long out_size) {
    int gw   = (blockIdx.x * blockDim.x + threadIdx.x) >> 5;
    int lane = threadIdx.x & 31;
    if (gw >= NB) return;
    unsigned int start = (gw == 0) ? 0u : g_incl[gw - 1];
    unsigned int n     = g_incl[gw] - start;
    if (n == 0) return;
    int is64 = g_is64;
    int sh = is64 ? 13 : 12;
    const long long off_ei = OFF_EI;
    const long long off_em = off_ei + 2ll * E;

    if (n <= 32) {
        unsigned int v = (lane < (int)n) ? g_low[start + lane] : 0xFFFFFFFFu;
        #pragma unroll
        for (int k = 2; k <= 32; k <<= 1) {
            #pragma unroll
            for (int j = k >> 1; j > 0; j >>= 1) {
                unsigned int o = __shfl_xor_sync(0xFFFFFFFFu, v, j);
                bool dirUp = ((lane & k) == 0);
                bool lower = ((lane & j) == 0);
                unsigned int mn = v < o ? v : o, mx = v < o ? o : v;
                v = (lower == dirUp) ? mn : mx;
            }
        }
        unsigned int prev = __shfl_up_sync(0xFFFFFFFFu, v, 1);
        if (lane < (int)n) {
            bool first = (lane == 0) || (v != prev);
            unsigned long long uk = (((unsigned long long)(unsigned int)gw) << sh) | v;
            float sf, df; bool valid;
            decode_key(uk, is64, &sf, &df, &valid);
            bool mask = first && valid;
            long long p = (long long)(start + lane);
            if (off_ei + p < out_size)     out[off_ei + p]     = mask ? sf   : -1.0f;
            if (off_ei + E + p < out_size) out[off_ei + E + p] = mask ? df   : -1.0f;
            if (off_em + p < out_size)     out[off_em + p]     = mask ? 1.0f : 0.0f;
        }
    } else {
        // rare (sentinel bucket ~100 entries): warp odd-even in global
        unsigned int* a = g_low + start;
        unsigned int eq = 1;
        unsigned int v0 = a[0];
        for (unsigned int i = lane; i < n; i += 32)
            if (a[i] != v0) eq = 0;
        eq = __all_sync(0xFFFFFFFFu, eq);
        if (!eq) {
            for (unsigned int pass = 0; pass < n; ++pass) {
                unsigned int st = pass & 1u;
                for (unsigned int i = st + 2u * lane; i + 1 < n; i += 64u) {
                    unsigned int x0 = a[i], x1 = a[i + 1];
                    if (x0 > x1) { a[i] = x1; a[i + 1] = x0; }
                }
                __syncwarp();
            }
        }
        for (unsigned int i = lane; i < n; i += 32) {
            unsigned int v = a[i];
            bool first = (i == 0) || (v != a[i - 1]);
            unsigned long long uk = (((unsigned long long)(unsigned int)gw) << sh) | v;
            float sf, df; bool valid;
            decode_key(uk, is64, &sf, &df, &valid);
            bool mask = first && valid;
            long long p = (long long)(start + i);
            if (off_ei + p < out_size)     out[off_ei + p]     = mask ? sf   : -1.0f;
            if (off_ei + E + p < out_size) out[off_ei + E + p] = mask ? df   : -1.0f;
            if (off_em + p < out_size)     out[off_em + p]     = mask ? 1.0f : 0.0f;
        }
    }
}

__global__ void finalize_kernel(float* __restrict__ out, long long out_size) {
    int i = blockIdx.x * blockDim.x + threadIdx.x;
    if (i >= KC * DIM) return;
    {
        int c = i / DIM;
        float v = (g_counts[c] > 0u) ? dec_f32(g_xmax[i]) : 0.0f;
        if (i < out_size) out[i] = v;
    }
    if (i < KC * 3) {
        int c = i / 3;
        unsigned int cnt = g_counts[c];
        if (OFF_POS + i < out_size)
            out[OFF_POS + i] = g_possum[i] / (float)(cnt > 0u ? cnt : 1u);
    }
    if (i < KC) {
        if (OFF_BATCH + i < out_size) out[OFF_BATCH + i] = (float)(i / (NV0 * NV1));
        if (OFF_MASK + i < out_size)  out[OFF_MASK + i]  = (g_counts[i] > 0u) ? 1.0f : 0.0f;
    }
}

// ---------------------------------------------------------------------------
// Launch: identify inputs by element-count relations (permutation-proof)
// ---------------------------------------------------------------------------
extern "C" void kernel_launch(void* const* d_in, const int* in_sizes, int n_in,
                              void* d_out, int out_size) {
    int ib = 0;
    for (int i = 1; i < n_in && i < 4; i++)
        if (in_sizes[i] < in_sizes[ib]) ib = i;
    long long N = in_sizes[ib];
    int ix = -1, ip = -1, ie = -1;
    for (int i = 0; i < n_in && i < 4; i++) {
        if (i == ib) continue;
        long long s = in_sizes[i];
        if (s == 64 * N)     ix = i;
        else if (s == 3 * N) ip = i;
        else                 ie = i;
    }
    if (ix < 0 || ip < 0 || ie < 0) { ix = 0; ip = 1; ib = 2; ie = 3; }

    const float* x    = (const float*)d_in[ix];
    const float* pos  = (const float*)d_in[ip];
    const void*  bat  = d_in[ib];
    const void*  eidx = d_in[ie];
    float*       out  = (float*)d_out;

    int Ni = (int)N;
    int E  = in_sizes[ie] / 2;
    if (Ni > N_MAX) Ni = N_MAX;
    if (E > E_MAX)  E  = E_MAX;

    const int T = 256;
    sniff_kernel<<<1, 32>>>((const unsigned int*)eidx);
    init_kernel<<<(KC * DIM + T - 1) / T, T>>>();
    cluster_kernel<<<(Ni + T - 1) / T, T>>>(pos, bat, Ni);
    xmax_kernel<<<(int)(((size_t)Ni * 32 + T - 1) / T), T>>>(x, Ni);
    hist_kernel<<<(E + T - 1) / T, T>>>(eidx, Ni, E);
    scan1_kernel<<<NBLK, 1024>>>();
    scan2_kernel<<<1, 1024>>>();
    scan3_kernel<<<NB / 1024, 1024>>>();
    scatter_kernel<<<(E + T - 1) / T, T>>>(eidx, Ni, E);
    bucket_emit_kernel<<<NB / 8, T>>>(out, E, (long long)out_size);
    finalize_kernel<<<(KC * DIM + T - 1) / T, T>>>(out, (long long)out_size);
}

// round 8
// speedup vs baseline: 1.3822x; 1.0142x over previous
#include <cuda_runtime.h>
#include <stdint.h>

// ---------------------------------------------------------------------------
// Problem constants (DSEC 480x640, 4x4 voxels, B=4)
// ---------------------------------------------------------------------------
#define NV0 120
#define NV1 160
#define NBATCH 4
#define KC (NBATCH * NV0 * NV1)   /* 76800 */
#define DIM 64

#define N_MAX (1 << 20)
#define E_MAX (1 << 23)
#define NB (1 << 20)              /* sort buckets */
#define NBLK (NB / 1024)
#define ENC_NEG_INF 0x007FFFFFu

// int32-wrapped sentinel: (int32)(76800*76800) = 1603272704
#define SENT32 1603272704
#define SENT64 5898240000ull

// Output layout (float32 flatten, reference return order):
#define OFF_POS   (KC * DIM)
#define OFF_BATCH (OFF_POS + KC * 3)
#define OFF_MASK  (OFF_BATCH + KC)
#define OFF_EI    (OFF_MASK + KC)

// ---------------------------------------------------------------------------
// Static device scratch
// ---------------------------------------------------------------------------
__device__ int            g_is64;
__device__ int            g_cluster[N_MAX];
__device__ unsigned int   g_counts[KC];
__device__ float          g_possum[KC * 3];
__device__ unsigned int   g_xmax[KC * DIM];
__device__ unsigned int   g_key32[E_MAX];     // monotone u32 key (i32 fast path)
__device__ unsigned short g_low[E_MAX];       // low key bits grouped by bucket
__device__ unsigned int   g_bcnt[NB];
__device__ unsigned int   g_incl[NB];
__device__ unsigned int   g_cursor[NB];       // running exclusive offsets
__device__ unsigned int   g_bsum[NBLK];

__device__ __forceinline__ unsigned int enc_f32(float v) {
    unsigned int u = __float_as_uint(v);
    return (u & 0x80000000u) ? ~u : (u | 0x80000000u);
}
__device__ __forceinline__ float dec_f32(unsigned int u) {
    u = (u & 0x80000000u) ? (u & 0x7FFFFFFFu) : ~u;
    return __uint_as_float(u);
}
__device__ __forceinline__ int ld_id(const void* p, long long i, int is64) {
    return is64 ? (int)((const long long*)p)[i] : ((const int*)p)[i];
}
__device__ __forceinline__ int clampi(int v, int lo, int hi) {
    return v < lo ? lo : (v > hi ? hi : v);
}

// monotone u64 key matching reference ascending order, ALL edges included
__device__ __forceinline__ unsigned long long edge_uk(int sc, int dc, int is64) {
    if (is64) {
        if (sc == dc) return SENT64;
        return (unsigned long long)(unsigned int)sc * 76800ull
             + (unsigned long long)(unsigned int)dc;
    }
    int key32 = (sc == dc) ? SENT32
              : (int)((unsigned int)sc * 76800u + (unsigned int)dc);  // wraps like ref
    return (unsigned long long)(((unsigned int)key32) ^ 0x80000000u); // signed order
}

__device__ __forceinline__ void decode_key(unsigned long long uk, int is64,
                                           float* sf, float* df, bool* valid) {
    if (is64) {
        *valid = (uk < SENT64);
        *sf = (float)(long long)(uk / 76800ull);
        *df = (float)(long long)(uk % 76800ull);
    } else {
        long long key = (long long)(int)(((unsigned int)uk) ^ 0x80000000u);
        *valid = (key < (long long)SENT32);
        long long q = key / 76800ll, r = key - q * 76800ll;
        if (r < 0) { q -= 1; r += 76800ll; }   // floor-div (jnp //, %)
        *sf = (float)q;
        *df = (float)r;
    }
}

// ---------------------------------------------------------------------------
__global__ void sniff_kernel(const unsigned int* ew) {
    if (threadIdx.x == 0) {
        unsigned int o = 0;
        for (int k = 1; k < 128; k += 2) o |= ew[k];
        g_is64 = (o == 0u) ? 1 : 0;
    }
}

__global__ void init_kernel() {
    int stride = gridDim.x * blockDim.x;
    for (int i = blockIdx.x * blockDim.x + threadIdx.x; i < KC * DIM; i += stride) {
        g_xmax[i] = ENC_NEG_INF;
        if (i < KC)     g_counts[i] = 0u;
        if (i < KC * 3) g_possum[i] = 0.0f;
        if (i < NB)     g_bcnt[i] = 0u;
    }
}

__global__ void cluster_kernel(const float* pos, const void* batch, int N) {
    int i = blockIdx.x * blockDim.x + threadIdx.x;
    if (i >= N) return;
    int is64 = g_is64;
    float p0 = pos[3 * i + 0];
    float p1 = pos[3 * i + 1];
    float p2 = pos[3 * i + 2];
    int c0 = clampi((int)floorf(p1 * 0.25f), 0, NV0 - 1);
    int c1 = clampi((int)floorf(p2 * 0.25f), 0, NV1 - 1);
    int b  = clampi(ld_id(batch, i, is64), 0, NBATCH - 1);
    int c  = c0 + c1 * NV0 + b * (NV0 * NV1);
    g_cluster[i] = c;
    atomicAdd(&g_counts[c], 1u);
    atomicAdd(&g_possum[3 * c + 0], p0);
    atomicAdd(&g_possum[3 * c + 1], p1);
    atomicAdd(&g_possum[3 * c + 2], p2);
}

// one warp per 2 nodes: float4 loads (LDG.128), 4 atomics per lane
__global__ void xmax_kernel(const float* __restrict__ x, int N) {
    int gw   = (blockIdx.x * blockDim.x + threadIdx.x) >> 5;
    int lane = threadIdx.x & 31;
    int node = gw * 2 + (lane >> 4);
    if (node >= N) return;
    int c = g_cluster[node];
    int l = lane & 15;
    float4 v = ((const float4*)(x + (size_t)node * DIM))[l];
    unsigned int* dst = g_xmax + (size_t)c * DIM + 4 * l;
    atomicMax(dst + 0, enc_f32(v.x));
    atomicMax(dst + 1, enc_f32(v.y));
    atomicMax(dst + 2, enc_f32(v.z));
    atomicMax(dst + 3, enc_f32(v.w));
}

// compute key once: store u32 key (i32 path) + histogram
__global__ void edgekey_kernel(const void* eidx, int N, int E) {
    int e = blockIdx.x * blockDim.x + threadIdx.x;
    if (e >= E) return;
    int is64 = g_is64;
    int u = clampi(ld_id(eidx, e, is64), 0, N - 1);
    int v = clampi(ld_id(eidx, (long long)E + e, is64), 0, N - 1);
    unsigned long long uk = edge_uk(g_cluster[u], g_cluster[v], is64);
    if (!is64) g_key32[e] = (unsigned int)uk;
    int sh = is64 ? 13 : 12;
    unsigned int b = (unsigned int)(uk >> sh);
    if (b < NB) atomicAdd(&g_bcnt[b], 1u);
}

// -- shfl-based scans ------------------------------------------------------
__device__ __forceinline__ unsigned int blk_incl_scan_1024(unsigned int v,
                                                           unsigned int* wsum) {
    int t = threadIdx.x;
    #pragma unroll
    for (int d = 1; d < 32; d <<= 1) {
        unsigned int u = __shfl_up_sync(0xFFFFFFFFu, v, d);
        if ((t & 31) >= d) v += u;
    }
    if ((t & 31) == 31) wsum[t >> 5] = v;
    __syncthreads();
    if (t < 32) {
        unsigned int s = wsum[t];
        #pragma unroll
        for (int d = 1; d < 32; d <<= 1) {
            unsigned int u = __shfl_up_sync(0xFFFFFFFFu, s, d);
            if (t >= d) s += u;
        }
        wsum[t] = s;
    }
    __syncthreads();
    if (t >= 32) v += wsum[(t >> 5) - 1];
    return v;
}

__global__ void scan1_kernel() {
    __shared__ unsigned int wsum[32];
    int base = blockIdx.x * 1024;
    unsigned int v = blk_incl_scan_1024(g_bcnt[base + threadIdx.x], wsum);
    g_incl[base + threadIdx.x] = v;
    if (threadIdx.x == 1023) g_bsum[blockIdx.x] = v;
}
__global__ void scan2_kernel() {
    __shared__ unsigned int wsum[32];
    unsigned int orig = g_bsum[threadIdx.x];
    unsigned int v = blk_incl_scan_1024(orig, wsum);
    g_bsum[threadIdx.x] = v - orig;   // exclusive
}
__global__ void scan3_kernel() {      // finalize incl + preload cursors
    int i = blockIdx.x * blockDim.x + threadIdx.x;
    if (i >= NB) return;
    unsigned int incl = g_incl[i] + g_bsum[i >> 10];
    g_incl[i]   = incl;
    g_cursor[i] = incl - g_bcnt[i];   // exclusive start
}

// stream keys; one random atomic per edge
__global__ void scatter_kernel(const void* eidx, int N, int E) {
    int e = blockIdx.x * blockDim.x + threadIdx.x;
    if (e >= E) return;
    int is64 = g_is64;
    unsigned long long uk;
    if (!is64) {
        uk = (unsigned long long)g_key32[e];
    } else {
        int u = clampi(ld_id(eidx, e, 1), 0, N - 1);
        int v = clampi(ld_id(eidx, (long long)E + e, 1), 0, N - 1);
        uk = edge_uk(g_cluster[u], g_cluster[v], 1);
    }
    int sh = is64 ? 13 : 12;
    unsigned int b   = (unsigned int)(uk >> sh);
    unsigned int low = (unsigned int)(uk & ((1u << sh) - 1u));
    if (b >= NB) return;
    unsigned int pos = atomicAdd(&g_cursor[b], 1u);
    if (pos < (unsigned int)E) g_low[pos] = (unsigned short)low;
}

// one WARP per bucket: adaptive-width register bitonic via shfl
__global__ void bucket_emit_kernel(float* __restrict__ out, int E, long long out_size) {
    int gw   = (blockIdx.x * blockDim.x + threadIdx.x) >> 5;
    int lane = threadIdx.x & 31;
    if (gw >= NB) return;
    unsigned int start = (gw == 0) ? 0u : g_incl[gw - 1];
    unsigned int n     = g_incl[gw] - start;
    if (n == 0) return;
    int is64 = g_is64;
    int sh = is64 ? 13 : 12;
    const long long off_ei = OFF_EI;
    const long long off_em = off_ei + 2ll * E;

    if (n == 1) {
        if (lane == 0) {
            unsigned long long uk = (((unsigned long long)(unsigned int)gw) << sh)
                                  | (unsigned int)g_low[start];
            float sf, df; bool valid;
            decode_key(uk, is64, &sf, &df, &valid);
            long long p = (long long)start;
            if (off_ei + p < out_size)     out[off_ei + p]     = valid ? sf   : -1.0f;
            if (off_ei + E + p < out_size) out[off_ei + E + p] = valid ? df   : -1.0f;
            if (off_em + p < out_size)     out[off_em + p]     = valid ? 1.0f : 0.0f;
        }
        return;
    }

    if (n <= 32) {
        unsigned int w = 2;
        while (w < n) w <<= 1;                 // warp-uniform sort width
        unsigned int v = (lane < (int)n) ? (unsigned int)g_low[start + lane]
                                         : 0xFFFFFFFFu;
        for (unsigned int k = 2; k <= w; k <<= 1) {
            for (unsigned int j = k >> 1; j > 0; j >>= 1) {
                unsigned int o = __shfl_xor_sync(0xFFFFFFFFu, v, j);
                bool dirUp = ((lane & k) == 0);
                bool lower = ((lane & j) == 0);
                unsigned int mn = v < o ? v : o, mx = v < o ? o : v;
                v = (lower == dirUp) ? mn : mx;
            }
        }
        unsigned int prev = __shfl_up_sync(0xFFFFFFFFu, v, 1);
        if (lane < (int)n) {
            bool first = (lane == 0) || (v != prev);
            unsigned long long uk = (((unsigned long long)(unsigned int)gw) << sh) | v;
            float sf, df; bool valid;
            decode_key(uk, is64, &sf, &df, &valid);
            bool mask = first && valid;
            long long p = (long long)(start + lane);
            if (off_ei + p < out_size)     out[off_ei + p]     = mask ? sf   : -1.0f;
            if (off_ei + E + p < out_size) out[off_ei + E + p] = mask ? df   : -1.0f;
            if (off_em + p < out_size)     out[off_em + p]     = mask ? 1.0f : 0.0f;
        }
    } else {
        // rare (sentinel bucket ~100 entries): warp odd-even in global (u16)
        unsigned short* a = g_low + start;
        unsigned int eq = 1;
        unsigned short v0 = a[0];
        for (unsigned int i = lane; i < n; i += 32)
            if (a[i] != v0) eq = 0;
        eq = __all_sync(0xFFFFFFFFu, eq);
        if (!eq) {
            for (unsigned int pass = 0; pass < n; ++pass) {
                unsigned int st = pass & 1u;
                for (unsigned int i = st + 2u * lane; i + 1 < n; i += 64u) {
                    unsigned short x0 = a[i], x1 = a[i + 1];
                    if (x0 > x1) { a[i] = x1; a[i + 1] = x0; }
                }
                __syncwarp();
            }
        }
        for (unsigned int i = lane; i < n; i += 32) {
            unsigned int v = a[i];
            bool first = (i == 0) || (v != (unsigned int)a[i - 1]);
            unsigned long long uk = (((unsigned long long)(unsigned int)gw) << sh) | v;
            float sf, df; bool valid;
            decode_key(uk, is64, &sf, &df, &valid);
            bool mask = first && valid;
            long long p = (long long)(start + i);
            if (off_ei + p < out_size)     out[off_ei + p]     = mask ? sf   : -1.0f;
            if (off_ei + E + p < out_size) out[off_ei + E + p] = mask ? df   : -1.0f;
            if (off_em + p < out_size)     out[off_em + p]     = mask ? 1.0f : 0.0f;
        }
    }
}

__global__ void finalize_kernel(float* __restrict__ out, long long out_size) {
    int i = blockIdx.x * blockDim.x + threadIdx.x;
    if (i >= KC * DIM) return;
    {
        int c = i / DIM;
        float v = (g_counts[c] > 0u) ? dec_f32(g_xmax[i]) : 0.0f;
        if (i < out_size) out[i] = v;
    }
    if (i < KC * 3) {
        int c = i / 3;
        unsigned int cnt = g_counts[c];
        if (OFF_POS + i < out_size)
            out[OFF_POS + i] = g_possum[i] / (float)(cnt > 0u ? cnt : 1u);
    }
    if (i < KC) {
        if (OFF_BATCH + i < out_size) out[OFF_BATCH + i] = (float)(i / (NV0 * NV1));
        if (OFF_MASK + i < out_size)  out[OFF_MASK + i]  = (g_counts[i] > 0u) ? 1.0f : 0.0f;
    }
}

// ---------------------------------------------------------------------------
// Launch: identify inputs by element-count relations (permutation-proof)
// ---------------------------------------------------------------------------
extern "C" void kernel_launch(void* const* d_in, const int* in_sizes, int n_in,
                              void* d_out, int out_size) {
    int ib = 0;
    for (int i = 1; i < n_in && i < 4; i++)
        if (in_sizes[i] < in_sizes[ib]) ib = i;
    long long N = in_sizes[ib];
    int ix = -1, ip = -1, ie = -1;
    for (int i = 0; i < n_in && i < 4; i++) {
        if (i == ib) continue;
        long long s = in_sizes[i];
        if (s == 64 * N)     ix = i;
        else if (s == 3 * N) ip = i;
        else                 ie = i;
    }
    if (ix < 0 || ip < 0 || ie < 0) { ix = 0; ip = 1; ib = 2; ie = 3; }

    const float* x    = (const float*)d_in[ix];
    const float* pos  = (const float*)d_in[ip];
    const void*  bat  = d_in[ib];
    const void*  eidx = d_in[ie];
    float*       out  = (float*)d_out;

    int Ni = (int)N;
    int E  = in_sizes[ie] / 2;
    if (Ni > N_MAX) Ni = N_MAX;
    if (E > E_MAX)  E  = E_MAX;

    const int T = 256;
    sniff_kernel<<<1, 32>>>((const unsigned int*)eidx);
    init_kernel<<<(KC * DIM + T - 1) / T, T>>>();
    cluster_kernel<<<(Ni + T - 1) / T, T>>>(pos, bat, Ni);
    xmax_kernel<<<(int)(((size_t)((Ni + 1) / 2) * 32 + T - 1) / T), T>>>(x, Ni);
    edgekey_kernel<<<(E + T - 1) / T, T>>>(eidx, Ni, E);
    scan1_kernel<<<NBLK, 1024>>>();
    scan2_kernel<<<1, 1024>>>();
    scan3_kernel<<<NB / 1024, 1024>>>();
    scatter_kernel<<<(E + T - 1) / T, T>>>(eidx, Ni, E);
    bucket_emit_kernel<<<NB / 8, T>>>(out, E, (long long)out_size);
    finalize_kernel<<<(KC * DIM + T - 1) / T, T>>>(out, (long long)out_size);
}

// round 9
// speedup vs baseline: 1.8748x; 1.3564x over previous
#include <cuda_runtime.h>
#include <stdint.h>

// ---------------------------------------------------------------------------
// Problem constants (DSEC 480x640, 4x4 voxels, B=4)
// ---------------------------------------------------------------------------
#define NV0 120
#define NV1 160
#define NBATCH 4
#define KC (NBATCH * NV0 * NV1)   /* 76800 */
#define DIM 64

#define N_MAX (1 << 20)
#define E_MAX (1 << 23)
#define NB (1 << 20)              /* sort buckets */
#define NBLK (NB / 1024)
#define ENC_NEG_INF 0x007FFFFFu

// int32-wrapped sentinel: (int32)(76800*76800) = 1603272704
#define SENT32 1603272704
#define SENT64 5898240000ull

// Output layout (float32 flatten, reference return order):
#define OFF_POS   (KC * DIM)
#define OFF_BATCH (OFF_POS + KC * 3)
#define OFF_MASK  (OFF_BATCH + KC)
#define OFF_EI    (OFF_MASK + KC)

// ---------------------------------------------------------------------------
// Static device scratch
// ---------------------------------------------------------------------------
__device__ int            g_is64;
__device__ int            g_cluster[N_MAX];
__device__ unsigned int   g_counts[KC];
__device__ float          g_possum[KC * 3];
__device__ unsigned int   g_xmax[KC * DIM];
__device__ unsigned int   g_key32[E_MAX];     // monotone u32 key (i32 fast path)
__device__ unsigned short g_low[E_MAX];       // low key bits grouped by bucket
__device__ unsigned int   g_bcnt[NB];
__device__ unsigned int   g_incl[NB];
__device__ unsigned int   g_cursor[NB];       // running exclusive offsets
__device__ unsigned int   g_bsum[NBLK];

__device__ __forceinline__ unsigned int enc_f32(float v) {
    unsigned int u = __float_as_uint(v);
    return (u & 0x80000000u) ? ~u : (u | 0x80000000u);
}
__device__ __forceinline__ float dec_f32(unsigned int u) {
    u = (u & 0x80000000u) ? (u & 0x7FFFFFFFu) : ~u;
    return __uint_as_float(u);
}
__device__ __forceinline__ int ld_id(const void* p, long long i, int is64) {
    return is64 ? (int)((const long long*)p)[i] : ((const int*)p)[i];
}
__device__ __forceinline__ int clampi(int v, int lo, int hi) {
    return v < lo ? lo : (v > hi ? hi : v);
}

// monotone u64 key matching reference ascending order, ALL edges included
__device__ __forceinline__ unsigned long long edge_uk(int sc, int dc, int is64) {
    if (is64) {
        if (sc == dc) return SENT64;
        return (unsigned long long)(unsigned int)sc * 76800ull
             + (unsigned long long)(unsigned int)dc;
    }
    int key32 = (sc == dc) ? SENT32
              : (int)((unsigned int)sc * 76800u + (unsigned int)dc);  // wraps like ref
    return (unsigned long long)(((unsigned int)key32) ^ 0x80000000u); // signed order
}

__device__ __forceinline__ void decode_key(unsigned long long uk, int is64,
                                           float* sf, float* df, bool* valid) {
    if (is64) {
        *valid = (uk < SENT64);
        *sf = (float)(long long)(uk / 76800ull);
        *df = (float)(long long)(uk % 76800ull);
    } else {
        long long key = (long long)(int)(((unsigned int)uk) ^ 0x80000000u);
        *valid = (key < (long long)SENT32);
        long long q = key / 76800ll, r = key - q * 76800ll;
        if (r < 0) { q -= 1; r += 76800ll; }   // floor-div (jnp //, %)
        *sf = (float)q;
        *df = (float)r;
    }
}

// emit one sorted run element (shared by all emit paths)
__device__ __forceinline__ void emit_pos(float* __restrict__ out, int E,
                                         long long out_size, unsigned int bucket,
                                         int sh, int is64, unsigned int v,
                                         bool first, long long p) {
    const long long off_ei = OFF_EI;
    const long long off_em = off_ei + 2ll * E;
    unsigned long long uk = (((unsigned long long)bucket) << sh) | v;
    float sf, df; bool valid;
    decode_key(uk, is64, &sf, &df, &valid);
    bool mask = first && valid;
    if (off_ei + p < out_size)     out[off_ei + p]     = mask ? sf   : -1.0f;
    if (off_ei + E + p < out_size) out[off_ei + E + p] = mask ? df   : -1.0f;
    if (off_em + p < out_size)     out[off_em + p]     = mask ? 1.0f : 0.0f;
}

// ---------------------------------------------------------------------------
// init (+ dtype sniff in block 0): int64 ids < 2^31 => odd 32-bit words all 0
// ---------------------------------------------------------------------------
__global__ void init_kernel(const unsigned int* ew) {
    int i = blockIdx.x * blockDim.x + threadIdx.x;
    if (i == 0) {
        unsigned int o = 0;
        for (int k = 1; k < 128; k += 2) o |= ew[k];
        g_is64 = (o == 0u) ? 1 : 0;
    }
    if (i >= KC * DIM) return;
    g_xmax[i] = ENC_NEG_INF;
    if (i < KC)     g_counts[i] = 0u;
    if (i < KC * 3) g_possum[i] = 0.0f;
    if (i < NB)     g_bcnt[i] = 0u;
}

// ---------------------------------------------------------------------------
// fused node kernel: one warp per node (cluster + counts + possum + x-max)
// ---------------------------------------------------------------------------
__global__ void node_kernel(const float* __restrict__ x,
                            const float* __restrict__ pos,
                            const void* batch, int N) {
    int gw   = (blockIdx.x * blockDim.x + threadIdx.x) >> 5;
    int lane = threadIdx.x & 31;
    if (gw >= N) return;
    int is64 = g_is64;
    // broadcast loads (single sector per warp)
    float p0 = pos[3 * gw + 0];
    float p1 = pos[3 * gw + 1];
    float p2 = pos[3 * gw + 2];
    int b  = clampi(ld_id(batch, gw, is64), 0, NBATCH - 1);
    int c0 = clampi((int)floorf(p1 * 0.25f), 0, NV0 - 1);
    int c1 = clampi((int)floorf(p2 * 0.25f), 0, NV1 - 1);
    int c  = c0 + c1 * NV0 + b * (NV0 * NV1);
    if (lane == 0) {
        g_cluster[gw] = c;
        atomicAdd(&g_counts[c], 1u);
        atomicAdd(&g_possum[3 * c + 0], p0);
        atomicAdd(&g_possum[3 * c + 1], p1);
        atomicAdd(&g_possum[3 * c + 2], p2);
    }
    float2 v = ((const float2*)(x + (size_t)gw * DIM))[lane];
    unsigned int* dst = g_xmax + (size_t)c * DIM;
    atomicMax(&dst[2 * lane],     enc_f32(v.x));
    atomicMax(&dst[2 * lane + 1], enc_f32(v.y));
}

// compute key once: store u32 key (i32 path) + histogram
__global__ void edgekey_kernel(const void* eidx, int N, int E) {
    int e = blockIdx.x * blockDim.x + threadIdx.x;
    if (e >= E) return;
    int is64 = g_is64;
    int u = clampi(ld_id(eidx, e, is64), 0, N - 1);
    int v = clampi(ld_id(eidx, (long long)E + e, is64), 0, N - 1);
    unsigned long long uk = edge_uk(g_cluster[u], g_cluster[v], is64);
    if (!is64) g_key32[e] = (unsigned int)uk;
    int sh = is64 ? 13 : 12;
    unsigned int b = (unsigned int)(uk >> sh);
    if (b < NB) atomicAdd(&g_bcnt[b], 1u);
}

// -- shfl-based scans ------------------------------------------------------
__device__ __forceinline__ unsigned int blk_incl_scan_1024(unsigned int v,
                                                           unsigned int* wsum) {
    int t = threadIdx.x;
    #pragma unroll
    for (int d = 1; d < 32; d <<= 1) {
        unsigned int u = __shfl_up_sync(0xFFFFFFFFu, v, d);
        if ((t & 31) >= d) v += u;
    }
    if ((t & 31) == 31) wsum[t >> 5] = v;
    __syncthreads();
    if (t < 32) {
        unsigned int s = wsum[t];
        #pragma unroll
        for (int d = 1; d < 32; d <<= 1) {
            unsigned int u = __shfl_up_sync(0xFFFFFFFFu, s, d);
            if (t >= d) s += u;
        }
        wsum[t] = s;
    }
    __syncthreads();
    if (t >= 32) v += wsum[(t >> 5) - 1];
    return v;
}

__global__ void scan1_kernel() {
    __shared__ unsigned int wsum[32];
    int base = blockIdx.x * 1024;
    unsigned int v = blk_incl_scan_1024(g_bcnt[base + threadIdx.x], wsum);
    g_incl[base + threadIdx.x] = v;
    if (threadIdx.x == 1023) g_bsum[blockIdx.x] = v;
}
__global__ void scan2_kernel() {
    __shared__ unsigned int wsum[32];
    unsigned int orig = g_bsum[threadIdx.x];
    unsigned int v = blk_incl_scan_1024(orig, wsum);
    g_bsum[threadIdx.x] = v - orig;   // exclusive
}
__global__ void scan3_kernel() {      // finalize incl + preload cursors
    int i = blockIdx.x * blockDim.x + threadIdx.x;
    if (i >= NB) return;
    unsigned int incl = g_incl[i] + g_bsum[i >> 10];
    g_incl[i]   = incl;
    g_cursor[i] = incl - g_bcnt[i];   // exclusive start
}

// stream keys; one random atomic per edge
__global__ void scatter_kernel(const void* eidx, int N, int E) {
    int e = blockIdx.x * blockDim.x + threadIdx.x;
    if (e >= E) return;
    int is64 = g_is64;
    unsigned long long uk;
    if (!is64) {
        uk = (unsigned long long)g_key32[e];
    } else {
        int u = clampi(ld_id(eidx, e, 1), 0, N - 1);
        int v = clampi(ld_id(eidx, (long long)E + e, 1), 0, N - 1);
        uk = edge_uk(g_cluster[u], g_cluster[v], 1);
    }
    int sh = is64 ? 13 : 12;
    unsigned int b   = (unsigned int)(uk >> sh);
    unsigned int low = (unsigned int)(uk & ((1u << sh) - 1u));
    if (b >= NB) return;
    unsigned int pos = atomicAdd(&g_cursor[b], 1u);
    if (pos < (unsigned int)E) g_low[pos] = (unsigned short)low;
}

// full-warp path for one bucket (n <= 32: 32-wide bitonic; else odd-even)
__device__ void emit_bucket_fullwarp(float* __restrict__ out, int E,
                                     long long out_size, unsigned int bucket,
                                     unsigned int start, unsigned int n,
                                     int sh, int is64, int lane) {
    if (n <= 32) {
        unsigned int v = (lane < (int)n) ? (unsigned int)g_low[start + lane]
                                         : 0xFFFFFFFFu;
        #pragma unroll
        for (unsigned int k = 2; k <= 32; k <<= 1) {
            for (unsigned int j = k >> 1; j > 0; j >>= 1) {
                unsigned int o = __shfl_xor_sync(0xFFFFFFFFu, v, j);
                bool dirUp = ((lane & k) == 0);
                bool lower = ((lane & j) == 0);
                unsigned int mn = v < o ? v : o, mx = v < o ? o : v;
                v = (lower == dirUp) ? mn : mx;
            }
        }
        unsigned int prev = __shfl_up_sync(0xFFFFFFFFu, v, 1);
        if (lane < (int)n) {
            bool first = (lane == 0) || (v != prev);
            emit_pos(out, E, out_size, bucket, sh, is64, v, first,
                     (long long)(start + lane));
        }
    } else {
        unsigned short* a = g_low + start;
        unsigned int eq = 1;
        unsigned short v0 = a[0];
        for (unsigned int i = lane; i < n; i += 32)
            if (a[i] != v0) eq = 0;
        eq = __all_sync(0xFFFFFFFFu, eq);
        if (!eq) {
            for (unsigned int pass = 0; pass < n; ++pass) {
                unsigned int st = pass & 1u;
                for (unsigned int i = st + 2u * lane; i + 1 < n; i += 64u) {
                    unsigned short x0 = a[i], x1 = a[i + 1];
                    if (x0 > x1) { a[i] = x1; a[i + 1] = x0; }
                }
                __syncwarp();
            }
        }
        for (unsigned int i = lane; i < n; i += 32) {
            unsigned int v = a[i];
            bool first = (i == 0) || (v != (unsigned int)a[i - 1]);
            emit_pos(out, E, out_size, bucket, sh, is64, v, first,
                     (long long)(start + i));
        }
    }
}

// TWO buckets per warp: 16-lane sub-warp bitonic for n<=16 (99.6% of buckets)
__global__ void bucket_emit_kernel(float* __restrict__ out, int E, long long out_size) {
    int gw   = (blockIdx.x * blockDim.x + threadIdx.x) >> 5;
    int lane = threadIdx.x & 31;
    unsigned int b0 = (unsigned int)gw * 2u;
    if (b0 >= NB) return;
    unsigned int start0 = (b0 == 0u) ? 0u : g_incl[b0 - 1];
    unsigned int end0   = g_incl[b0];
    unsigned int end1   = g_incl[b0 + 1];
    unsigned int n0 = end0 - start0, n1 = end1 - end0;
    if ((n0 | n1) == 0u) return;
    int is64 = g_is64;
    int sh = is64 ? 13 : 12;

    if (n0 <= 16u && n1 <= 16u) {
        int half = lane >> 4, l = lane & 15;
        unsigned int start  = half ? end0 : start0;
        unsigned int n      = half ? n1 : n0;
        unsigned int bucket = b0 + (unsigned int)half;
        unsigned int v = ((unsigned int)l < n) ? (unsigned int)g_low[start + l]
                                               : 0xFFFFFFFFu;
        // width-16 bitonic; xor j<=8 never crosses the 16-lane boundary
        #pragma unroll
        for (unsigned int k = 2; k <= 16; k <<= 1) {
            for (unsigned int j = k >> 1; j > 0; j >>= 1) {
                unsigned int o = __shfl_xor_sync(0xFFFFFFFFu, v, j);
                bool dirUp = (((unsigned int)l & k) == 0);
                bool lower = (((unsigned int)l & j) == 0);
                unsigned int mn = v < o ? v : o, mx = v < o ? o : v;
                v = (lower == dirUp) ? mn : mx;
            }
        }
        unsigned int prev = __shfl_up_sync(0xFFFFFFFFu, v, 1);
        if ((unsigned int)l < n) {
            bool first = (l == 0) || (v != prev);
            emit_pos(out, E, out_size, bucket, sh, is64, v, first,
                     (long long)(start + (unsigned int)l));
        }
    } else {
        if (n0) emit_bucket_fullwarp(out, E, out_size, b0,     start0, n0, sh, is64, lane);
        if (n1) emit_bucket_fullwarp(out, E, out_size, b0 + 1, end0,   n1, sh, is64, lane);
    }
}

__global__ void finalize_kernel(float* __restrict__ out, long long out_size) {
    int i = blockIdx.x * blockDim.x + threadIdx.x;
    if (i >= KC * DIM) return;
    {
        int c = i / DIM;
        float v = (g_counts[c] > 0u) ? dec_f32(g_xmax[i]) : 0.0f;
        if (i < out_size) out[i] = v;
    }
    if (i < KC * 3) {
        int c = i / 3;
        unsigned int cnt = g_counts[c];
        if (OFF_POS + i < out_size)
            out[OFF_POS + i] = g_possum[i] / (float)(cnt > 0u ? cnt : 1u);
    }
    if (i < KC) {
        if (OFF_BATCH + i < out_size) out[OFF_BATCH + i] = (float)(i / (NV0 * NV1));
        if (OFF_MASK + i < out_size)  out[OFF_MASK + i]  = (g_counts[i] > 0u) ? 1.0f : 0.0f;
    }
}

// ---------------------------------------------------------------------------
// Launch: identify inputs by element-count relations (permutation-proof)
// ---------------------------------------------------------------------------
extern "C" void kernel_launch(void* const* d_in, const int* in_sizes, int n_in,
                              void* d_out, int out_size) {
    int ib = 0;
    for (int i = 1; i < n_in && i < 4; i++)
        if (in_sizes[i] < in_sizes[ib]) ib = i;
    long long N = in_sizes[ib];
    int ix = -1, ip = -1, ie = -1;
    for (int i = 0; i < n_in && i < 4; i++) {
        if (i == ib) continue;
        long long s = in_sizes[i];
        if (s == 64 * N)     ix = i;
        else if (s == 3 * N) ip = i;
        else                 ie = i;
    }
    if (ix < 0 || ip < 0 || ie < 0) { ix = 0; ip = 1; ib = 2; ie = 3; }

    const float* x    = (const float*)d_in[ix];
    const float* pos  = (const float*)d_in[ip];
    const void*  bat  = d_in[ib];
    const void*  eidx = d_in[ie];
    float*       out  = (float*)d_out;

    int Ni = (int)N;
    int E  = in_sizes[ie] / 2;
    if (Ni > N_MAX) Ni = N_MAX;
    if (E > E_MAX)  E  = E_MAX;

    const int T = 256;
    init_kernel<<<(KC * DIM + T - 1) / T, T>>>((const unsigned int*)eidx);
    node_kernel<<<(int)(((size_t)Ni * 32 + T - 1) / T), T>>>(x, pos, bat, Ni);
    edgekey_kernel<<<(E + T - 1) / T, T>>>(eidx, Ni, E);
    scan1_kernel<<<NBLK, 1024>>>();
    scan2_kernel<<<1, 1024>>>();
    scan3_kernel<<<NB / 1024, 1024>>>();
    scatter_kernel<<<(E + T - 1) / T, T>>>(eidx, Ni, E);
    bucket_emit_kernel<<<NB / 16, T>>>(out, E, (long long)out_size);
    finalize_kernel<<<(KC * DIM + T - 1) / T, T>>>(out, (long long)out_size);
}

// round 10
// speedup vs baseline: 1.9545x; 1.0425x over previous
#include <cuda_runtime.h>
#include <stdint.h>

// ---------------------------------------------------------------------------
// Problem constants (DSEC 480x640, 4x4 voxels, B=4)
// ---------------------------------------------------------------------------
#define NV0 120
#define NV1 160
#define NBATCH 4
#define KC (NBATCH * NV0 * NV1)   /* 76800 */
#define DIM 64

#define N_MAX (1 << 20)
#define E_MAX (1 << 23)
#define NB (1 << 20)              /* sort buckets */
#define NBLK (NB / 1024)
#define ENC_NEG_INF 0x007FFFFFu

// int32-wrapped sentinel: (int32)(76800*76800) = 1603272704
#define SENT32 1603272704
#define SENT64 5898240000ull
// biased (unsigned-order) sentinel: SENT32 ^ 0x80000000 = SENT32 + 2^31
#define USENT32 3750756352u

// Output layout (float32 flatten, reference return order):
#define OFF_POS   (KC * DIM)
#define OFF_BATCH (OFF_POS + KC * 3)
#define OFF_MASK  (OFF_BATCH + KC)
#define OFF_EI    (OFF_MASK + KC)

// ---------------------------------------------------------------------------
// Static device scratch
// ---------------------------------------------------------------------------
__device__ int            g_is64;
__device__ int            g_cluster[N_MAX];
__device__ unsigned int   g_counts[KC];
__device__ float          g_possum[KC * 3];
__device__ unsigned int   g_xmax[KC * DIM];
__device__ unsigned int   g_key32[E_MAX];     // monotone u32 key (i32 fast path)
__device__ unsigned short g_low[E_MAX];       // low key bits grouped by bucket
__device__ unsigned int   g_bcnt[NB];
__device__ unsigned int   g_incl[NB];
__device__ unsigned int   g_cursor[NB];       // running exclusive offsets
__device__ unsigned int   g_bsum[NBLK];

__device__ __forceinline__ unsigned int enc_f32(float v) {
    unsigned int u = __float_as_uint(v);
    return (u & 0x80000000u) ? ~u : (u | 0x80000000u);
}
__device__ __forceinline__ float dec_f32(unsigned int u) {
    u = (u & 0x80000000u) ? (u & 0x7FFFFFFFu) : ~u;
    return __uint_as_float(u);
}
__device__ __forceinline__ int ld_id(const void* p, long long i, int is64) {
    return is64 ? (int)((const long long*)p)[i] : ((const int*)p)[i];
}
__device__ __forceinline__ int clampi(int v, int lo, int hi) {
    return v < lo ? lo : (v > hi ? hi : v);
}

// monotone u64 key matching reference ascending order, ALL edges included
__device__ __forceinline__ unsigned long long edge_uk(int sc, int dc, int is64) {
    if (is64) {
        if (sc == dc) return SENT64;
        return (unsigned long long)(unsigned int)sc * 76800ull
             + (unsigned long long)(unsigned int)dc;
    }
    int key32 = (sc == dc) ? SENT32
              : (int)((unsigned int)sc * 76800u + (unsigned int)dc);  // wraps like ref
    return (unsigned long long)(((unsigned int)key32) ^ 0x80000000u); // signed order
}

// i32 fast path: decode biased key via magic division (no 64-bit div).
// 76800 = 2^10 * 75;  floor(uk/76800) = umulhi(uk>>10, ceil(2^32/75)=57266231)
// (exact: error 29*x/2^32 < 1/75 gap for x < 2^22).
// signed floor-div: 2^31 = 76800*27962 + 2048.
__device__ __forceinline__ void decode32(unsigned int uk,
                                         float* sf, float* df, bool* valid) {
    *valid = (uk < USENT32);
    unsigned int q = __umulhi(uk >> 10, 57266231u);
    unsigned int r = uk - q * 76800u;
    int qf; unsigned int rf;
    if (r >= 2048u) { qf = (int)q - 27962; rf = r - 2048u; }
    else            { qf = (int)q - 27963; rf = r + 74752u; }
    *sf = (float)qf;
    *df = (float)rf;
}

__device__ __forceinline__ void decode_key(unsigned long long uk, int is64,
                                           float* sf, float* df, bool* valid) {
    if (is64) {
        *valid = (uk < SENT64);
        *sf = (float)(long long)(uk / 76800ull);
        *df = (float)(long long)(uk % 76800ull);
    } else {
        decode32((unsigned int)uk, sf, df, valid);
    }
}

// emit one sorted run element (shared by all emit paths)
__device__ __forceinline__ void emit_pos(float* __restrict__ out, int E,
                                         long long out_size, unsigned int bucket,
                                         int sh, int is64, unsigned int v,
                                         bool first, long long p) {
    const long long off_ei = OFF_EI;
    const long long off_em = off_ei + 2ll * E;
    unsigned long long uk = (((unsigned long long)bucket) << sh) | v;
    float sf, df; bool valid;
    decode_key(uk, is64, &sf, &df, &valid);
    bool mask = first && valid;
    if (off_ei + p < out_size)     out[off_ei + p]     = mask ? sf   : -1.0f;
    if (off_ei + E + p < out_size) out[off_ei + E + p] = mask ? df   : -1.0f;
    if (off_em + p < out_size)     out[off_em + p]     = mask ? 1.0f : 0.0f;
}

// ---------------------------------------------------------------------------
// init (+ dtype sniff): vectorized uint4 stores
// ---------------------------------------------------------------------------
__global__ void init_kernel(const unsigned int* ew) {
    int i = blockIdx.x * blockDim.x + threadIdx.x;
    if (i == 0) {
        unsigned int o = 0;
        for (int k = 1; k < 128; k += 2) o |= ew[k];
        g_is64 = (o == 0u) ? 1 : 0;
    }
    if (i >= KC * DIM / 4) return;
    ((uint4*)g_xmax)[i] = make_uint4(ENC_NEG_INF, ENC_NEG_INF, ENC_NEG_INF, ENC_NEG_INF);
    if (i < KC / 4)     ((uint4*)g_counts)[i] = make_uint4(0u, 0u, 0u, 0u);
    if (i < KC * 3 / 4) ((uint4*)g_possum)[i] = make_uint4(0u, 0u, 0u, 0u);
    if (i < NB / 4)     ((uint4*)g_bcnt)[i]   = make_uint4(0u, 0u, 0u, 0u);
}

// ---------------------------------------------------------------------------
// fused node kernel: one warp per node (cluster + counts + possum + x-max)
// ---------------------------------------------------------------------------
__global__ void node_kernel(const float* __restrict__ x,
                            const float* __restrict__ pos,
                            const void* batch, int N) {
    int gw   = (blockIdx.x * blockDim.x + threadIdx.x) >> 5;
    int lane = threadIdx.x & 31;
    if (gw >= N) return;
    int is64 = g_is64;
    float p0 = pos[3 * gw + 0];
    float p1 = pos[3 * gw + 1];
    float p2 = pos[3 * gw + 2];
    int b  = clampi(ld_id(batch, gw, is64), 0, NBATCH - 1);
    int c0 = clampi((int)floorf(p1 * 0.25f), 0, NV0 - 1);
    int c1 = clampi((int)floorf(p2 * 0.25f), 0, NV1 - 1);
    int c  = c0 + c1 * NV0 + b * (NV0 * NV1);
    if (lane == 0) {
        g_cluster[gw] = c;
        atomicAdd(&g_counts[c], 1u);
        atomicAdd(&g_possum[3 * c + 0], p0);
        atomicAdd(&g_possum[3 * c + 1], p1);
        atomicAdd(&g_possum[3 * c + 2], p2);
    }
    float2 v = ((const float2*)(x + (size_t)gw * DIM))[lane];
    unsigned int* dst = g_xmax + (size_t)c * DIM;
    atomicMax(&dst[2 * lane],     enc_f32(v.x));
    atomicMax(&dst[2 * lane + 1], enc_f32(v.y));
}

// ---------------------------------------------------------------------------
// edgekey: 2 edges per thread (i32 fast path), store key + histogram
// ---------------------------------------------------------------------------
__global__ void edgekey_kernel(const void* eidx, int N, int E) {
    int t = blockIdx.x * blockDim.x + threadIdx.x;
    int is64 = g_is64;
    if (!is64) {
        int npair = E >> 1;                 // E is even in practice
        if (t < npair) {
            const int2* r0 = (const int2*)eidx;
            const int2* r1 = (const int2*)((const int*)eidx + E);
            int2 uu = r0[t], vv = r1[t];
            int u0 = clampi(uu.x, 0, N - 1), u1 = clampi(uu.y, 0, N - 1);
            int v0 = clampi(vv.x, 0, N - 1), v1 = clampi(vv.y, 0, N - 1);
            int sc0 = g_cluster[u0], dc0 = g_cluster[v0];
            int sc1 = g_cluster[u1], dc1 = g_cluster[v1];
            unsigned int k0 = (unsigned int)edge_uk(sc0, dc0, 0);
            unsigned int k1 = (unsigned int)edge_uk(sc1, dc1, 0);
            ((uint2*)g_key32)[t] = make_uint2(k0, k1);
            atomicAdd(&g_bcnt[k0 >> 12], 1u);
            atomicAdd(&g_bcnt[k1 >> 12], 1u);
        }
        // odd tail
        if (t == 0 && (E & 1)) {
            int e = E - 1;
            int u = clampi(((const int*)eidx)[e], 0, N - 1);
            int v = clampi(((const int*)eidx)[(size_t)E + e], 0, N - 1);
            unsigned int k = (unsigned int)edge_uk(g_cluster[u], g_cluster[v], 0);
            g_key32[e] = k;
            atomicAdd(&g_bcnt[k >> 12], 1u);
        }
    } else {
        if (t >= E) return;
        int u = clampi(ld_id(eidx, t, 1), 0, N - 1);
        int v = clampi(ld_id(eidx, (long long)E + t, 1), 0, N - 1);
        unsigned long long uk = edge_uk(g_cluster[u], g_cluster[v], 1);
        unsigned int b = (unsigned int)(uk >> 13);
        if (b < NB) atomicAdd(&g_bcnt[b], 1u);
    }
}

// -- shfl-based scans ------------------------------------------------------
__device__ __forceinline__ unsigned int blk_incl_scan_1024(unsigned int v,
                                                           unsigned int* wsum) {
    int t = threadIdx.x;
    #pragma unroll
    for (int d = 1; d < 32; d <<= 1) {
        unsigned int u = __shfl_up_sync(0xFFFFFFFFu, v, d);
        if ((t & 31) >= d) v += u;
    }
    if ((t & 31) == 31) wsum[t >> 5] = v;
    __syncthreads();
    if (t < 32) {
        unsigned int s = wsum[t];
        #pragma unroll
        for (int d = 1; d < 32; d <<= 1) {
            unsigned int u = __shfl_up_sync(0xFFFFFFFFu, s, d);
            if (t >= d) s += u;
        }
        wsum[t] = s;
    }
    __syncthreads();
    if (t >= 32) v += wsum[(t >> 5) - 1];
    return v;
}

__global__ void scan1_kernel() {
    __shared__ unsigned int wsum[32];
    int base = blockIdx.x * 1024;
    unsigned int v = blk_incl_scan_1024(g_bcnt[base + threadIdx.x], wsum);
    g_incl[base + threadIdx.x] = v;
    if (threadIdx.x == 1023) g_bsum[blockIdx.x] = v;
}
__global__ void scan2_kernel() {
    __shared__ unsigned int wsum[32];
    unsigned int orig = g_bsum[threadIdx.x];
    unsigned int v = blk_incl_scan_1024(orig, wsum);
    g_bsum[threadIdx.x] = v - orig;   // exclusive
}
__global__ void scan3_kernel() {      // finalize incl + preload cursors
    int i = blockIdx.x * blockDim.x + threadIdx.x;
    if (i >= NB) return;
    unsigned int incl = g_incl[i] + g_bsum[i >> 10];
    g_incl[i]   = incl;
    g_cursor[i] = incl - g_bcnt[i];   // exclusive start
}

// ---------------------------------------------------------------------------
// scatter: 4 edges per thread (uint4 key load), 4 independent atomic chains
// ---------------------------------------------------------------------------
__global__ void scatter_kernel(const void* eidx, int N, int E) {
    int t = blockIdx.x * blockDim.x + threadIdx.x;
    int is64 = g_is64;
    if (!is64) {
        int nquad = E >> 2;
        if (t < nquad) {
            uint4 k = ((const uint4*)g_key32)[t];
            unsigned int p0 = atomicAdd(&g_cursor[k.x >> 12], 1u);
            unsigned int p1 = atomicAdd(&g_cursor[k.y >> 12], 1u);
            unsigned int p2 = atomicAdd(&g_cursor[k.z >> 12], 1u);
            unsigned int p3 = atomicAdd(&g_cursor[k.w >> 12], 1u);
            if (p0 < (unsigned int)E) g_low[p0] = (unsigned short)(k.x & 0xFFFu);
            if (p1 < (unsigned int)E) g_low[p1] = (unsigned short)(k.y & 0xFFFu);
            if (p2 < (unsigned int)E) g_low[p2] = (unsigned short)(k.z & 0xFFFu);
            if (p3 < (unsigned int)E) g_low[p3] = (unsigned short)(k.w & 0xFFFu);
        }
        if (t == 0) {
            for (int e = E & ~3; e < E; e++) {
                unsigned int k = g_key32[e];
                unsigned int p = atomicAdd(&g_cursor[k >> 12], 1u);
                if (p < (unsigned int)E) g_low[p] = (unsigned short)(k & 0xFFFu);
            }
        }
    } else {
        if (t >= E) return;
        int u = clampi(ld_id(eidx, t, 1), 0, N - 1);
        int v = clampi(ld_id(eidx, (long long)E + t, 1), 0, N - 1);
        unsigned long long uk = edge_uk(g_cluster[u], g_cluster[v], 1);
        unsigned int b   = (unsigned int)(uk >> 13);
        unsigned int low = (unsigned int)(uk & 0x1FFFu);
        if (b >= NB) return;
        unsigned int pos = atomicAdd(&g_cursor[b], 1u);
        if (pos < (unsigned int)E) g_low[pos] = (unsigned short)low;
    }
}

// full-warp path for one bucket (n <= 32: 32-wide bitonic; else odd-even)
__device__ void emit_bucket_fullwarp(float* __restrict__ out, int E,
                                     long long out_size, unsigned int bucket,
                                     unsigned int start, unsigned int n,
                                     int sh, int is64, int lane) {
    if (n <= 32) {
        unsigned int v = (lane < (int)n) ? (unsigned int)g_low[start + lane]
                                         : 0xFFFFFFFFu;
        #pragma unroll
        for (unsigned int k = 2; k <= 32; k <<= 1) {
            for (unsigned int j = k >> 1; j > 0; j >>= 1) {
                unsigned int o = __shfl_xor_sync(0xFFFFFFFFu, v, j);
                bool dirUp = ((lane & k) == 0);
                bool lower = ((lane & j) == 0);
                unsigned int mn = v < o ? v : o, mx = v < o ? o : v;
                v = (lower == dirUp) ? mn : mx;
            }
        }
        unsigned int prev = __shfl_up_sync(0xFFFFFFFFu, v, 1);
        if (lane < (int)n) {
            bool first = (lane == 0) || (v != prev);
            emit_pos(out, E, out_size, bucket, sh, is64, v, first,
                     (long long)(start + lane));
        }
    } else {
        unsigned short* a = g_low + start;
        unsigned int eq = 1;
        unsigned short v0 = a[0];
        for (unsigned int i = lane; i < n; i += 32)
            if (a[i] != v0) eq = 0;
        eq = __all_sync(0xFFFFFFFFu, eq);
        if (!eq) {
            for (unsigned int pass = 0; pass < n; ++pass) {
                unsigned int st = pass & 1u;
                for (unsigned int i = st + 2u * lane; i + 1 < n; i += 64u) {
                    unsigned short x0 = a[i], x1 = a[i + 1];
                    if (x0 > x1) { a[i] = x1; a[i + 1] = x0; }
                }
                __syncwarp();
            }
        }
        for (unsigned int i = lane; i < n; i += 32) {
            unsigned int v = a[i];
            bool first = (i == 0) || (v != (unsigned int)a[i - 1]);
            emit_pos(out, E, out_size, bucket, sh, is64, v, first,
                     (long long)(start + i));
        }
    }
}

// TWO buckets per warp: 16-lane sub-warp bitonic for n<=16 (99.6% of buckets)
__global__ void bucket_emit_kernel(float* __restrict__ out, int E, long long out_size) {
    int gw   = (blockIdx.x * blockDim.x + threadIdx.x) >> 5;
    int lane = threadIdx.x & 31;
    unsigned int b0 = (unsigned int)gw * 2u;
    if (b0 >= NB) return;
    unsigned int start0 = (b0 == 0u) ? 0u : g_incl[b0 - 1];
    unsigned int end0   = g_incl[b0];
    unsigned int end1   = g_incl[b0 + 1];
    unsigned int n0 = end0 - start0, n1 = end1 - end0;
    if ((n0 | n1) == 0u) return;
    int is64 = g_is64;
    int sh = is64 ? 13 : 12;

    if (n0 <= 16u && n1 <= 16u) {
        int half = lane >> 4, l = lane & 15;
        unsigned int start  = half ? end0 : start0;
        unsigned int n      = half ? n1 : n0;
        unsigned int bucket = b0 + (unsigned int)half;
        unsigned int v = ((unsigned int)l < n) ? (unsigned int)g_low[start + l]
                                               : 0xFFFFFFFFu;
        #pragma unroll
        for (unsigned int k = 2; k <= 16; k <<= 1) {
            for (unsigned int j = k >> 1; j > 0; j >>= 1) {
                unsigned int o = __shfl_xor_sync(0xFFFFFFFFu, v, j);
                bool dirUp = (((unsigned int)l & k) == 0);
                bool lower = (((unsigned int)l & j) == 0);
                unsigned int mn = v < o ? v : o, mx = v < o ? o : v;
                v = (lower == dirUp) ? mn : mx;
            }
        }
        unsigned int prev = __shfl_up_sync(0xFFFFFFFFu, v, 1);
        if ((unsigned int)l < n) {
            bool first = (l == 0) || (v != prev);
            emit_pos(out, E, out_size, bucket, sh, is64, v, first,
                     (long long)(start + (unsigned int)l));
        }
    } else {
        if (n0) emit_bucket_fullwarp(out, E, out_size, b0,     start0, n0, sh, is64, lane);
        if (n1) emit_bucket_fullwarp(out, E, out_size, b0 + 1, end0,   n1, sh, is64, lane);
    }
}

__global__ void finalize_kernel(float* __restrict__ out, long long out_size) {
    int i = blockIdx.x * blockDim.x + threadIdx.x;
    if (i >= KC * DIM) return;
    {
        int c = i / DIM;
        float v = (g_counts[c] > 0u) ? dec_f32(g_xmax[i]) : 0.0f;
        if (i < out_size) out[i] = v;
    }
    if (i < KC * 3) {
        int c = i / 3;
        unsigned int cnt = g_counts[c];
        if (OFF_POS + i < out_size)
            out[OFF_POS + i] = g_possum[i] / (float)(cnt > 0u ? cnt : 1u);
    }
    if (i < KC) {
        if (OFF_BATCH + i < out_size) out[OFF_BATCH + i] = (float)(i / (NV0 * NV1));
        if (OFF_MASK + i < out_size)  out[OFF_MASK + i]  = (g_counts[i] > 0u) ? 1.0f : 0.0f;
    }
}

// ---------------------------------------------------------------------------
// Launch: identify inputs by element-count relations (permutation-proof)
// ---------------------------------------------------------------------------
extern "C" void kernel_launch(void* const* d_in, const int* in_sizes, int n_in,
                              void* d_out, int out_size) {
    int ib = 0;
    for (int i = 1; i < n_in && i < 4; i++)
        if (in_sizes[i] < in_sizes[ib]) ib = i;
    long long N = in_sizes[ib];
    int ix = -1, ip = -1, ie = -1;
    for (int i = 0; i < n_in && i < 4; i++) {
        if (i == ib) continue;
        long long s = in_sizes[i];
        if (s == 64 * N)     ix = i;
        else if (s == 3 * N) ip = i;
        else                 ie = i;
    }
    if (ix < 0 || ip < 0 || ie < 0) { ix = 0; ip = 1; ib = 2; ie = 3; }

    const float* x    = (const float*)d_in[ix];
    const float* pos  = (const float*)d_in[ip];
    const void*  bat  = d_in[ib];
    const void*  eidx = d_in[ie];
    float*       out  = (float*)d_out;

    int Ni = (int)N;
    int E  = in_sizes[ie] / 2;
    if (Ni > N_MAX) Ni = N_MAX;
    if (E > E_MAX)  E  = E_MAX;

    const int T = 256;
    init_kernel<<<(KC * DIM / 4 + T - 1) / T, T>>>((const unsigned int*)eidx);
    node_kernel<<<(int)(((size_t)Ni * 32 + T - 1) / T), T>>>(x, pos, bat, Ni);
    {   // edgekey: E/2 threads (i32) but must also cover is64 path (E threads)
        int thr = E;  // covers both paths; i32 threads beyond E/2 exit early
        edgekey_kernel<<<(thr + T - 1) / T, T>>>(eidx, Ni, E);
    }
    scan1_kernel<<<NBLK, 1024>>>();
    scan2_kernel<<<1, 1024>>>();
    scan3_kernel<<<NB / 1024, 1024>>>();
    scatter_kernel<<<(E + T - 1) / T, T>>>(eidx, Ni, E);
    bucket_emit_kernel<<<NB / 16, T>>>(out, E, (long long)out_size);
    finalize_kernel<<<(KC * DIM + T - 1) / T, T>>>(out, (long long)out_size);
}

// round 11
// speedup vs baseline: 1.9796x; 1.0129x over previous
#include <cuda_runtime.h>
#include <stdint.h>

// ---------------------------------------------------------------------------
// Problem constants (DSEC 480x640, 4x4 voxels, B=4)
// ---------------------------------------------------------------------------
#define NV0 120
#define NV1 160
#define NBATCH 4
#define KC (NBATCH * NV0 * NV1)   /* 76800 */
#define DIM 64

#define N_MAX (1 << 20)
#define E_MAX (1 << 23)
#define NB (1 << 20)              /* sort buckets */
#define NBLK (NB / 1024)
#define ENC_NEG_INF 0x007FFFFFu

// int32-wrapped sentinel: (int32)(76800*76800) = 1603272704
#define SENT32 1603272704
#define SENT64 5898240000ull
// biased (unsigned-order) sentinel: SENT32 ^ 0x80000000
#define USENT32 3750756352u

// Output layout (float32 flatten, reference return order):
#define OFF_POS   (KC * DIM)
#define OFF_BATCH (OFF_POS + KC * 3)
#define OFF_MASK  (OFF_BATCH + KC)
#define OFF_EI    (OFF_MASK + KC)

// ---------------------------------------------------------------------------
// Static device scratch
// ---------------------------------------------------------------------------
__device__ int            g_is64;
__device__ int            g_cluster[N_MAX];
__device__ unsigned int   g_counts[KC];
__device__ float          g_possum[KC * 3];
__device__ unsigned int   g_xmax[KC * DIM];
__device__ unsigned int   g_key32[E_MAX];     // monotone u32 key (i32 fast path)
__device__ unsigned short g_low[E_MAX];       // low key bits grouped by bucket
__device__ unsigned int   g_bcnt[NB];
__device__ unsigned int   g_incl[NB];
__device__ unsigned int   g_cursor[NB];       // running exclusive offsets
__device__ unsigned int   g_bsum[NBLK];

__device__ __forceinline__ unsigned int enc_f32(float v) {
    unsigned int u = __float_as_uint(v);
    return (u & 0x80000000u) ? ~u : (u | 0x80000000u);
}
__device__ __forceinline__ float dec_f32(unsigned int u) {
    u = (u & 0x80000000u) ? (u & 0x7FFFFFFFu) : ~u;
    return __uint_as_float(u);
}
__device__ __forceinline__ int ld_id(const void* p, long long i, int is64) {
    return is64 ? (int)((const long long*)p)[i] : ((const int*)p)[i];
}
__device__ __forceinline__ int clampi(int v, int lo, int hi) {
    return v < lo ? lo : (v > hi ? hi : v);
}

// monotone u64 key matching reference ascending order, ALL edges included
__device__ __forceinline__ unsigned long long edge_uk(int sc, int dc, int is64) {
    if (is64) {
        if (sc == dc) return SENT64;
        return (unsigned long long)(unsigned int)sc * 76800ull
             + (unsigned long long)(unsigned int)dc;
    }
    int key32 = (sc == dc) ? SENT32
              : (int)((unsigned int)sc * 76800u + (unsigned int)dc);  // wraps like ref
    return (unsigned long long)(((unsigned int)key32) ^ 0x80000000u); // signed order
}

// i32 fast path: decode biased key via magic division (no 64-bit div).
// 76800 = 2^10 * 75;  floor(uk/76800) = umulhi(uk>>10, 57266231)  (exact)
// signed floor-div: 2^31 = 76800*27962 + 2048.
__device__ __forceinline__ void decode32(unsigned int uk,
                                         float* sf, float* df, bool* valid) {
    *valid = (uk < USENT32);
    unsigned int q = __umulhi(uk >> 10, 57266231u);
    unsigned int r = uk - q * 76800u;
    int qf; unsigned int rf;
    if (r >= 2048u) { qf = (int)q - 27962; rf = r - 2048u; }
    else            { qf = (int)q - 27963; rf = r + 74752u; }
    *sf = (float)qf;
    *df = (float)rf;
}

__device__ __forceinline__ void decode_key(unsigned long long uk, int is64,
                                           float* sf, float* df, bool* valid) {
    if (is64) {
        *valid = (uk < SENT64);
        *sf = (float)(long long)(uk / 76800ull);
        *df = (float)(long long)(uk % 76800ull);
    } else {
        decode32((unsigned int)uk, sf, df, valid);
    }
}

// emit one sorted run element (shared by all emit paths)
__device__ __forceinline__ void emit_pos(float* __restrict__ out, int E,
                                         long long out_size, unsigned int bucket,
                                         int sh, int is64, unsigned int v,
                                         bool first, long long p) {
    const long long off_ei = OFF_EI;
    const long long off_em = off_ei + 2ll * E;
    unsigned long long uk = (((unsigned long long)bucket) << sh) | v;
    float sf, df; bool valid;
    decode_key(uk, is64, &sf, &df, &valid);
    bool mask = first && valid;
    if (off_ei + p < out_size)     out[off_ei + p]     = mask ? sf   : -1.0f;
    if (off_ei + E + p < out_size) out[off_ei + E + p] = mask ? df   : -1.0f;
    if (off_em + p < out_size)     out[off_em + p]     = mask ? 1.0f : 0.0f;
}

// ---------------------------------------------------------------------------
// init (+ dtype sniff): vectorized uint4 stores
// ---------------------------------------------------------------------------
__global__ void init_kernel(const unsigned int* ew) {
    int i = blockIdx.x * blockDim.x + threadIdx.x;
    if (i == 0) {
        unsigned int o = 0;
        for (int k = 1; k < 128; k += 2) o |= ew[k];
        g_is64 = (o == 0u) ? 1 : 0;
    }
    if (i >= KC * DIM / 4) return;
    ((uint4*)g_xmax)[i] = make_uint4(ENC_NEG_INF, ENC_NEG_INF, ENC_NEG_INF, ENC_NEG_INF);
    if (i < KC / 4)     ((uint4*)g_counts)[i] = make_uint4(0u, 0u, 0u, 0u);
    if (i < KC * 3 / 4) ((uint4*)g_possum)[i] = make_uint4(0u, 0u, 0u, 0u);
    if (i < NB / 4)     ((uint4*)g_bcnt)[i]   = make_uint4(0u, 0u, 0u, 0u);
}

// ---------------------------------------------------------------------------
// cluster: one thread per node (must precede the stream fork)
// ---------------------------------------------------------------------------
__global__ void cluster_kernel(const float* __restrict__ pos,
                               const void* batch, int N) {
    int i = blockIdx.x * blockDim.x + threadIdx.x;
    if (i >= N) return;
    int is64 = g_is64;
    float p0 = pos[3 * i + 0];
    float p1 = pos[3 * i + 1];
    float p2 = pos[3 * i + 2];
    int c0 = clampi((int)floorf(p1 * 0.25f), 0, NV0 - 1);
    int c1 = clampi((int)floorf(p2 * 0.25f), 0, NV1 - 1);
    int b  = clampi(ld_id(batch, i, is64), 0, NBATCH - 1);
    int c  = c0 + c1 * NV0 + b * (NV0 * NV1);
    g_cluster[i] = c;
    atomicAdd(&g_counts[c], 1u);
    atomicAdd(&g_possum[3 * c + 0], p0);
    atomicAdd(&g_possum[3 * c + 1], p1);
    atomicAdd(&g_possum[3 * c + 2], p2);
}

// x scatter-max: one warp per node, float2 loads, 2 spread atomics per lane
// (round-7 proven form; runs on the side stream, DRAM-bound)
__global__ void xmax_kernel(const float* __restrict__ x, int N) {
    int gw   = (blockIdx.x * blockDim.x + threadIdx.x) >> 5;
    int lane = threadIdx.x & 31;
    if (gw >= N) return;
    int c = g_cluster[gw];
    float2 v = ((const float2*)(x + (size_t)gw * DIM))[lane];
    unsigned int* dst = g_xmax + (size_t)c * DIM;
    atomicMax(&dst[2 * lane],     enc_f32(v.x));
    atomicMax(&dst[2 * lane + 1], enc_f32(v.y));
}

// ---------------------------------------------------------------------------
// edgekey: 2 edges per thread (i32 fast path), store key + histogram
// ---------------------------------------------------------------------------
__global__ void edgekey_kernel(const void* eidx, int N, int E) {
    int t = blockIdx.x * blockDim.x + threadIdx.x;
    int is64 = g_is64;
    if (!is64) {
        int npair = E >> 1;
        if (t < npair) {
            const int2* r0 = (const int2*)eidx;
            const int2* r1 = (const int2*)((const int*)eidx + E);
            int2 uu = r0[t], vv = r1[t];
            int u0 = clampi(uu.x, 0, N - 1), u1 = clampi(uu.y, 0, N - 1);
            int v0 = clampi(vv.x, 0, N - 1), v1 = clampi(vv.y, 0, N - 1);
            int sc0 = g_cluster[u0], dc0 = g_cluster[v0];
            int sc1 = g_cluster[u1], dc1 = g_cluster[v1];
            unsigned int k0 = (unsigned int)edge_uk(sc0, dc0, 0);
            unsigned int k1 = (unsigned int)edge_uk(sc1, dc1, 0);
            ((uint2*)g_key32)[t] = make_uint2(k0, k1);
            atomicAdd(&g_bcnt[k0 >> 12], 1u);
            atomicAdd(&g_bcnt[k1 >> 12], 1u);
        }
        if (t == 0 && (E & 1)) {
            int e = E - 1;
            int u = clampi(((const int*)eidx)[e], 0, N - 1);
            int v = clampi(((const int*)eidx)[(size_t)E + e], 0, N - 1);
            unsigned int k = (unsigned int)edge_uk(g_cluster[u], g_cluster[v], 0);
            g_key32[e] = k;
            atomicAdd(&g_bcnt[k >> 12], 1u);
        }
    } else {
        if (t >= E) return;
        int u = clampi(ld_id(eidx, t, 1), 0, N - 1);
        int v = clampi(ld_id(eidx, (long long)E + t, 1), 0, N - 1);
        unsigned long long uk = edge_uk(g_cluster[u], g_cluster[v], 1);
        unsigned int b = (unsigned int)(uk >> 13);
        if (b < NB) atomicAdd(&g_bcnt[b], 1u);
    }
}

// -- shfl-based scans ------------------------------------------------------
__device__ __forceinline__ unsigned int blk_incl_scan_1024(unsigned int v,
                                                           unsigned int* wsum) {
    int t = threadIdx.x;
    #pragma unroll
    for (int d = 1; d < 32; d <<= 1) {
        unsigned int u = __shfl_up_sync(0xFFFFFFFFu, v, d);
        if ((t & 31) >= d) v += u;
    }
    if ((t & 31) == 31) wsum[t >> 5] = v;
    __syncthreads();
    if (t < 32) {
        unsigned int s = wsum[t];
        #pragma unroll
        for (int d = 1; d < 32; d <<= 1) {
            unsigned int u = __shfl_up_sync(0xFFFFFFFFu, s, d);
            if (t >= d) s += u;
        }
        wsum[t] = s;
    }
    __syncthreads();
    if (t >= 32) v += wsum[(t >> 5) - 1];
    return v;
}

__global__ void scan1_kernel() {
    __shared__ unsigned int wsum[32];
    int base = blockIdx.x * 1024;
    unsigned int v = blk_incl_scan_1024(g_bcnt[base + threadIdx.x], wsum);
    g_incl[base + threadIdx.x] = v;
    if (threadIdx.x == 1023) g_bsum[blockIdx.x] = v;
}
__global__ void scan2_kernel() {
    __shared__ unsigned int wsum[32];
    unsigned int orig = g_bsum[threadIdx.x];
    unsigned int v = blk_incl_scan_1024(orig, wsum);
    g_bsum[threadIdx.x] = v - orig;   // exclusive
}
__global__ void scan3_kernel() {      // finalize incl + preload cursors
    int i = blockIdx.x * blockDim.x + threadIdx.x;
    if (i >= NB) return;
    unsigned int incl = g_incl[i] + g_bsum[i >> 10];
    g_incl[i]   = incl;
    g_cursor[i] = incl - g_bcnt[i];   // exclusive start
}

// ---------------------------------------------------------------------------
// scatter: 4 edges per thread (uint4 key load), 4 independent atomic chains
// ---------------------------------------------------------------------------
__global__ void scatter_kernel(const void* eidx, int N, int E) {
    int t = blockIdx.x * blockDim.x + threadIdx.x;
    int is64 = g_is64;
    if (!is64) {
        int nquad = E >> 2;
        if (t < nquad) {
            uint4 k = ((const uint4*)g_key32)[t];
            unsigned int p0 = atomicAdd(&g_cursor[k.x >> 12], 1u);
            unsigned int p1 = atomicAdd(&g_cursor[k.y >> 12], 1u);
            unsigned int p2 = atomicAdd(&g_cursor[k.z >> 12], 1u);
            unsigned int p3 = atomicAdd(&g_cursor[k.w >> 12], 1u);
            if (p0 < (unsigned int)E) g_low[p0] = (unsigned short)(k.x & 0xFFFu);
            if (p1 < (unsigned int)E) g_low[p1] = (unsigned short)(k.y & 0xFFFu);
            if (p2 < (unsigned int)E) g_low[p2] = (unsigned short)(k.z & 0xFFFu);
            if (p3 < (unsigned int)E) g_low[p3] = (unsigned short)(k.w & 0xFFFu);
        }
        if (t == 0) {
            for (int e = E & ~3; e < E; e++) {
                unsigned int k = g_key32[e];
                unsigned int p = atomicAdd(&g_cursor[k >> 12], 1u);
                if (p < (unsigned int)E) g_low[p] = (unsigned short)(k & 0xFFFu);
            }
        }
    } else {
        if (t >= E) return;
        int u = clampi(ld_id(eidx, t, 1), 0, N - 1);
        int v = clampi(ld_id(eidx, (long long)E + t, 1), 0, N - 1);
        unsigned long long uk = edge_uk(g_cluster[u], g_cluster[v], 1);
        unsigned int b   = (unsigned int)(uk >> 13);
        unsigned int low = (unsigned int)(uk & 0x1FFFu);
        if (b >= NB) return;
        unsigned int pos = atomicAdd(&g_cursor[b], 1u);
        if (pos < (unsigned int)E) g_low[pos] = (unsigned short)low;
    }
}

// full-warp path for one bucket (n <= 32: 32-wide bitonic; else odd-even)
__device__ void emit_bucket_fullwarp(float* __restrict__ out, int E,
                                     long long out_size, unsigned int bucket,
                                     unsigned int start, unsigned int n,
                                     int sh, int is64, int lane) {
    if (n <= 32) {
        unsigned int v = (lane < (int)n) ? (unsigned int)g_low[start + lane]
                                         : 0xFFFFFFFFu;
        #pragma unroll
        for (unsigned int k = 2; k <= 32; k <<= 1) {
            for (unsigned int j = k >> 1; j > 0; j >>= 1) {
                unsigned int o = __shfl_xor_sync(0xFFFFFFFFu, v, j);
                bool dirUp = ((lane & k) == 0);
                bool lower = ((lane & j) == 0);
                unsigned int mn = v < o ? v : o, mx = v < o ? o : v;
                v = (lower == dirUp) ? mn : mx;
            }
        }
        unsigned int prev = __shfl_up_sync(0xFFFFFFFFu, v, 1);
        if (lane < (int)n) {
            bool first = (lane == 0) || (v != prev);
            emit_pos(out, E, out_size, bucket, sh, is64, v, first,
                     (long long)(start + lane));
        }
    } else {
        unsigned short* a = g_low + start;
        unsigned int eq = 1;
        unsigned short v0 = a[0];
        for (unsigned int i = lane; i < n; i += 32)
            if (a[i] != v0) eq = 0;
        eq = __all_sync(0xFFFFFFFFu, eq);
        if (!eq) {
            for (unsigned int pass = 0; pass < n; ++pass) {
                unsigned int st = pass & 1u;
                for (unsigned int i = st + 2u * lane; i + 1 < n; i += 64u) {
                    unsigned short x0 = a[i], x1 = a[i + 1];
                    if (x0 > x1) { a[i] = x1; a[i + 1] = x0; }
                }
                __syncwarp();
            }
        }
        for (unsigned int i = lane; i < n; i += 32) {
            unsigned int v = a[i];
            bool first = (i == 0) || (v != (unsigned int)a[i - 1]);
            emit_pos(out, E, out_size, bucket, sh, is64, v, first,
                     (long long)(start + i));
        }
    }
}

// TWO buckets per warp: 16-lane sub-warp bitonic for n<=16 (99.6% of buckets)
__global__ void bucket_emit_kernel(float* __restrict__ out, int E, long long out_size) {
    int gw   = (blockIdx.x * blockDim.x + threadIdx.x) >> 5;
    int lane = threadIdx.x & 31;
    unsigned int b0 = (unsigned int)gw * 2u;
    if (b0 >= NB) return;
    unsigned int start0 = (b0 == 0u) ? 0u : g_incl[b0 - 1];
    unsigned int end0   = g_incl[b0];
    unsigned int end1   = g_incl[b0 + 1];
    unsigned int n0 = end0 - start0, n1 = end1 - end0;
    if ((n0 | n1) == 0u) return;
    int is64 = g_is64;
    int sh = is64 ? 13 : 12;

    if (n0 <= 16u && n1 <= 16u) {
        int half = lane >> 4, l = lane & 15;
        unsigned int start  = half ? end0 : start0;
        unsigned int n      = half ? n1 : n0;
        unsigned int bucket = b0 + (unsigned int)half;
        unsigned int v = ((unsigned int)l < n) ? (unsigned int)g_low[start + l]
                                               : 0xFFFFFFFFu;
        #pragma unroll
        for (unsigned int k = 2; k <= 16; k <<= 1) {
            for (unsigned int j = k >> 1; j > 0; j >>= 1) {
                unsigned int o = __shfl_xor_sync(0xFFFFFFFFu, v, j);
                bool dirUp = (((unsigned int)l & k) == 0);
                bool lower = (((unsigned int)l & j) == 0);
                unsigned int mn = v < o ? v : o, mx = v < o ? o : v;
                v = (lower == dirUp) ? mn : mx;
            }
        }
        unsigned int prev = __shfl_up_sync(0xFFFFFFFFu, v, 1);
        if ((unsigned int)l < n) {
            bool first = (l == 0) || (v != prev);
            emit_pos(out, E, out_size, bucket, sh, is64, v, first,
                     (long long)(start + (unsigned int)l));
        }
    } else {
        if (n0) emit_bucket_fullwarp(out, E, out_size, b0,     start0, n0, sh, is64, lane);
        if (n1) emit_bucket_fullwarp(out, E, out_size, b0 + 1, end0,   n1, sh, is64, lane);
    }
}

__global__ void finalize_kernel(float* __restrict__ out, long long out_size) {
    int i = blockIdx.x * blockDim.x + threadIdx.x;
    if (i >= KC * DIM) return;
    {
        int c = i / DIM;
        float v = (g_counts[c] > 0u) ? dec_f32(g_xmax[i]) : 0.0f;
        if (i < out_size) out[i] = v;
    }
    if (i < KC * 3) {
        int c = i / 3;
        unsigned int cnt = g_counts[c];
        if (OFF_POS + i < out_size)
            out[OFF_POS + i] = g_possum[i] / (float)(cnt > 0u ? cnt : 1u);
    }
    if (i < KC) {
        if (OFF_BATCH + i < out_size) out[OFF_BATCH + i] = (float)(i / (NV0 * NV1));
        if (OFF_MASK + i < out_size)  out[OFF_MASK + i]  = (g_counts[i] > 0u) ? 1.0f : 0.0f;
    }
}

// ---------------------------------------------------------------------------
// Launch: fork-join streams — edge chain (L2-bound) || xmax chain (DRAM-bound)
// ---------------------------------------------------------------------------
extern "C" void kernel_launch(void* const* d_in, const int* in_sizes, int n_in,
                              void* d_out, int out_size) {
    int ib = 0;
    for (int i = 1; i < n_in && i < 4; i++)
        if (in_sizes[i] < in_sizes[ib]) ib = i;
    long long N = in_sizes[ib];
    int ix = -1, ip = -1, ie = -1;
    for (int i = 0; i < n_in && i < 4; i++) {
        if (i == ib) continue;
        long long s = in_sizes[i];
        if (s == 64 * N)     ix = i;
        else if (s == 3 * N) ip = i;
        else                 ie = i;
    }
    if (ix < 0 || ip < 0 || ie < 0) { ix = 0; ip = 1; ib = 2; ie = 3; }

    const float* x    = (const float*)d_in[ix];
    const float* pos  = (const float*)d_in[ip];
    const void*  bat  = d_in[ib];
    const void*  eidx = d_in[ie];
    float*       out  = (float*)d_out;

    int Ni = (int)N;
    int E  = in_sizes[ie] / 2;
    if (Ni > N_MAX) Ni = N_MAX;
    if (E > E_MAX)  E  = E_MAX;

    // lazily-created side stream + events (host objects; reused across calls)
    static cudaStream_t s1 = nullptr;
    static cudaEvent_t evFork = nullptr, evJoin = nullptr;
    if (!s1) {
        cudaStreamCreateWithFlags(&s1, cudaStreamNonBlocking);
        cudaEventCreateWithFlags(&evFork, cudaEventDisableTiming);
        cudaEventCreateWithFlags(&evJoin, cudaEventDisableTiming);
    }

    const int T = 256;
    init_kernel<<<(KC * DIM / 4 + T - 1) / T, T>>>((const unsigned int*)eidx);
    cluster_kernel<<<(Ni + T - 1) / T, T>>>(pos, bat, Ni);

    // fork: side stream runs the DRAM-bound x-max chain
    cudaEventRecord(evFork, 0);
    cudaStreamWaitEvent(s1, evFork, 0);
    xmax_kernel<<<(int)(((size_t)Ni * 32 + T - 1) / T), T, 0, s1>>>(x, Ni);
    finalize_kernel<<<(KC * DIM + T - 1) / T, T, 0, s1>>>(out, (long long)out_size);
    cudaEventRecord(evJoin, s1);

    // main stream: the L2-bound edge chain
    edgekey_kernel<<<(E + T - 1) / T, T>>>(eidx, Ni, E);
    scan1_kernel<<<NBLK, 1024>>>();
    scan2_kernel<<<1, 1024>>>();
    scan3_kernel<<<NB / 1024, 1024>>>();
    scatter_kernel<<<(E + T - 1) / T, T>>>(eidx, Ni, E);
    bucket_emit_kernel<<<NB / 16, T>>>(out, E, (long long)out_size);

    // join
    cudaStreamWaitEvent(0, evJoin, 0);
}